// round 13
// baseline (speedup 1.0000x reference)
#include <cuda_runtime.h>
#include <cuda_bf16.h>
#include <math.h>

#define Hdim 128
#define KNB  48
#define NT   256
typedef unsigned long long u64;

__device__ __nv_bfloat16 g_W1bh[128 * 384];   // [n][k] hi
__device__ __nv_bfloat16 g_W1bl[128 * 384];
__device__ __nv_bfloat16 g_W2h[128 * 128];
__device__ __nv_bfloat16 g_W2l[128 * 128];
__device__ __nv_bfloat16 g_W3h[128 * 128];
__device__ __nv_bfloat16 g_W3l[128 * 128];
__device__ __nv_bfloat16 g_Winh[512 * 128];   // [f][k]
__device__ __nv_bfloat16 g_Winl[512 * 128];
__device__ __nv_bfloat16 g_Wouth[128 * 512];  // [n][k]
__device__ __nv_bfloat16 g_Woutl[128 * 512];
__device__ float  g_hvc[4096 * 128];
__device__ float  g_dh[4096 * 128];
__device__ float  g_Hbuf[4096 * 128];

__device__ __forceinline__ float gelu_erf(float x) {
    return 0.5f * x * (1.0f + erff(x * 0.70710678118654752440f));
}
__device__ __forceinline__ unsigned pack2(__nv_bfloat16 a, __nv_bfloat16 b) {
    return ((unsigned)__bfloat16_as_ushort(b) << 16) | (unsigned)__bfloat16_as_ushort(a);
}
__device__ __forceinline__ void bsplit(float x, __nv_bfloat16& h, __nv_bfloat16& l) {
    h = __float2bfloat16_rn(x);
    l = __float2bfloat16_rn(x - __bfloat162float(h));
}
__device__ __forceinline__ void mma16816(float* c, const unsigned* a, const unsigned* b) {
    asm volatile(
        "mma.sync.aligned.m16n8k16.row.col.f32.bf16.bf16.f32 "
        "{%0,%1,%2,%3}, {%4,%5,%6,%7}, {%8,%9}, {%0,%1,%2,%3};"
        : "+f"(c[0]), "+f"(c[1]), "+f"(c[2]), "+f"(c[3])
        : "r"(a[0]), "r"(a[1]), "r"(a[2]), "r"(a[3]), "r"(b[0]), "r"(b[1]));
}
__device__ __forceinline__ void ldsm4(unsigned* r, unsigned addr) {
    asm volatile("ldmatrix.sync.aligned.m8n8.x4.shared.b16 {%0,%1,%2,%3}, [%4];"
        : "=r"(r[0]), "=r"(r[1]), "=r"(r[2]), "=r"(r[3]) : "r"(addr));
}

__global__ void prep_weights(const float* __restrict__ W1_w, const float* __restrict__ W2_w,
                             const float* __restrict__ W3_w, const float* __restrict__ Win_w,
                             const float* __restrict__ Wout_w) {
    int idx = blockIdx.x * blockDim.x + threadIdx.x;
    __nv_bfloat16 h, l;
    if (idx < 49152) {
        int n = idx / 384, k = idx % 384;
        bsplit(W1_w[n * 512 + 128 + k], h, l);
        g_W1bh[idx] = h; g_W1bl[idx] = l;
    } else if (idx < 65536) {
        int i = idx - 49152;
        bsplit(W2_w[i], h, l);
        g_W2h[i] = h; g_W2l[i] = l;
    } else if (idx < 81920) {
        int i = idx - 65536;
        bsplit(W3_w[i], h, l);
        g_W3h[i] = h; g_W3l[i] = l;
    } else if (idx < 147456) {
        int i = idx - 81920;
        bsplit(Win_w[i], h, l);
        g_Winh[i] = h; g_Winl[i] = l;
    } else if (idx < 212992) {
        int i = idx - 147456;
        bsplit(Wout_w[i], h, l);
        g_Wouth[i] = h; g_Woutl[i] = l;
    }
}

// hvc = h_V @ W1a^T + b1 (exact fp32); also zero g_dh
__global__ void __launch_bounds__(NT, 1)
hvc_kernel(const float* __restrict__ h_V, const float* __restrict__ W1_w,
           const float* __restrict__ W1_b) {
    extern __shared__ float smh[];
    float* sW  = smh;
    float* sHv = smh + 16384;
    const int tid = threadIdx.x;
    const int nb  = blockIdx.x * 8;
    #pragma unroll
    for (int i = 0; i < 16; ++i) {
        int id4 = i * NT + tid;
        int k4 = id4 >> 7, n = id4 & 127;
        float4 v = ((const float4*)(W1_w + (size_t)n * 512))[k4];
        sW[(4 * k4 + 0) * 128 + n] = v.x;
        sW[(4 * k4 + 1) * 128 + n] = v.y;
        sW[(4 * k4 + 2) * 128 + n] = v.z;
        sW[(4 * k4 + 3) * 128 + n] = v.w;
    }
    {
        int node = tid >> 5, q = tid & 31;
        float4 v = ((const float4*)(h_V + (size_t)(nb + node) * 128))[q];
        *(float4*)(sHv + node * 128 + 4 * q) = v;
        ((float4*)(g_dh + (size_t)nb * 128))[tid] = make_float4(0.f, 0.f, 0.f, 0.f);
    }
    __syncthreads();
    #pragma unroll
    for (int it = 0; it < 4; ++it) {
        int o = it * NT + tid;
        int node = o >> 7, col = o & 127;
        const float* hv = sHv + node * 128;
        float a = W1_b[col];
        #pragma unroll 8
        for (int k = 0; k < 128; ++k) a = fmaf(hv[k], sW[k * 128 + col], a);
        g_hvc[(size_t)(nb + node) * 128 + col] = a;
    }
}

// ---- shared chunk = [128 rows][36 b32] = 18432 B ----
#define CHB 18432
#define CHW (CHB / 4)

// stage one 64k B chunk from prepped bf16 [n][K]
__device__ __forceinline__ void stage_B2(char* smem, int sm_b, const __nv_bfloat16* gh,
                                         const __nv_bfloat16* gl, int K, int rowoff,
                                         int c, int tid) {
    unsigned* dh = (unsigned*)(smem + sm_b);
    unsigned* dl = dh + CHW;
    #pragma unroll
    for (int i = 0; i < 4; ++i) {
        int idx = i * NT + tid;
        int n = idx >> 3, q = idx & 7;
        uint4 vh = *(const uint4*)(gh + (size_t)(rowoff + n) * K + c * 64 + q * 8);
        uint4 vl = *(const uint4*)(gl + (size_t)(rowoff + n) * K + c * 64 + q * 8);
        int o = n * 36 + q * 4;
        *(uint4*)(dh + o) = vh;
        *(uint4*)(dl + o) = vl;
    }
}

// one 64k chunk: acc[64] += A(128x64) * B^T, split-bf16 (hh+hl+lh)
__device__ __forceinline__ void chunk_mma(unsigned sAh, unsigned sAl,
                                          unsigned sBh, unsigned sBl,
                                          float* acc, unsigned aoff, unsigned boff) {
    #pragma unroll
    for (int v = 0; v < 2; ++v) {
        unsigned ah[2][2][4], al[2][2][4];
        #pragma unroll
        for (int t = 0; t < 2; ++t)
            #pragma unroll
            for (int sl = 0; sl < 2; ++sl) {
                unsigned off = aoff + t * 2304 + (2 * v + sl) * 32;
                ldsm4(ah[t][sl], sAh + off);
                ldsm4(al[t][sl], sAl + off);
            }
        #pragma unroll
        for (int u = 0; u < 8; ++u) {
            unsigned bh4[4], bl4[4];
            unsigned off = boff + u * 1152 + v * 64;
            ldsm4(bh4, sBh + off);
            ldsm4(bl4, sBl + off);
            #pragma unroll
            for (int t = 0; t < 2; ++t) {
                float* cc = acc + (t * 8 + u) * 4;
                #pragma unroll
                for (int sl = 0; sl < 2; ++sl) {
                    mma16816(cc, ah[t][sl], bh4 + 2 * sl);
                    mma16816(cc, ah[t][sl], bl4 + 2 * sl);
                    mma16816(cc, al[t][sl], bh4 + 2 * sl);
                }
            }
        }
    }
}

// write acc (bias-added, gelu'd) into bf16 hi/lo chunks at base sm_y
__device__ __forceinline__ void epi_store(char* smem, int sm_y, const float* acc,
                                          const float* badd0, const float* badd1,
                                          int m0, int nb0, int g, int t4) {
    unsigned* y = (unsigned*)(smem + sm_y);
    #pragma unroll
    for (int t = 0; t < 2; ++t) {
        int r1 = m0 + t * 16 + g, r2 = r1 + 8;
        #pragma unroll
        for (int u = 0; u < 8; ++u) {
            int n = nb0 + u * 8 + 2 * t4;
            const float* cc = acc + (t * 8 + u) * 4;
            float ya = gelu_erf(cc[0] + badd0[n]);
            float yb = gelu_erf(cc[1] + badd0[n + 1]);
            float yc = gelu_erf(cc[2] + badd1[n]);
            float yd = gelu_erf(cc[3] + badd1[n + 1]);
            __nv_bfloat16 ha, la, hb, lb, hc, lc, hd, ld;
            bsplit(ya, ha, la); bsplit(yb, hb, lb);
            bsplit(yc, hc, lc); bsplit(yd, hd, ld);
            int ch = n >> 6, col = (n & 63) >> 1;
            unsigned* yh = y + (2 * ch) * CHW;
            unsigned* yl = y + (2 * ch + 1) * CHW;
            yh[r1 * 36 + col] = pack2(ha, hb);
            yl[r1 * 36 + col] = pack2(la, lb);
            yh[r2 * 36 + col] = pack2(hc, hd);
            yl[r2 * 36 + col] = pack2(lc, ld);
        }
    }
}

// ---- edge GEMM smem layout ----
#define SM_BIAS 0
#define SM_HVC  1024
#define SM_Y1   3072
#define SM_X    (SM_Y1 + 4 * CHB)
#define SM_B    (SM_X + 4 * CHB)
#define SM_TOT  (SM_B + 2 * CHB)

__global__ void __launch_bounds__(NT, 1)
edge_gemm_kernel(const float* __restrict__ h_E, const float* __restrict__ mask_attend,
                 const float* __restrict__ W2_b, const float* __restrict__ W3_b,
                 int n_nodes) {
    extern __shared__ char smem[];
    const int tid = threadIdx.x;
    const int wid = tid >> 5;
    const int lane = tid & 31;
    const int g = lane >> 2, t4 = lane & 3;
    const int wm = wid >> 1, wn = wid & 1;
    const int m0 = wm * 32, nb0 = wn * 64;
    const int base = blockIdx.x * 128;
    const int n0 = base / 48;
    const unsigned sb = (unsigned)__cvta_generic_to_shared(smem);

    const unsigned aoff = (m0 + (lane & 15)) * 144 + (lane >> 4) * 16;
    const unsigned boff = (nb0 + (lane & 7)) * 144 + (lane >> 3) * 16;

    if (tid < 128) {
        ((float*)(smem + SM_BIAS))[tid]       = W2_b[tid];
        ((float*)(smem + SM_BIAS))[128 + tid] = W3_b[tid];
    }
    for (int t = tid; t < 512; t += NT) {
        int gg = t >> 7, c = t & 127;
        int nd = n0 + gg;
        ((float*)(smem + SM_HVC))[t] = (nd < n_nodes) ? g_hvc[(size_t)nd * 128 + c] : 0.f;
    }

    float acc[64];
    #pragma unroll
    for (int i = 0; i < 64; ++i) acc[i] = 0.f;

    // ---------- GEMM1: h_E @ W1b^T, K=384 ----------
    for (int c = 0; c < 6; ++c) {
        __syncthreads();
        {
            unsigned* dh = (unsigned*)(smem + SM_X);
            unsigned* dl = dh + CHW;
            #pragma unroll
            for (int i = 0; i < 4; ++i) {
                int idx = i * NT + tid;
                int r = idx >> 3, q = idx & 7;
                const float4* p = (const float4*)(h_E + (size_t)(base + r) * 384 + c * 64 + q * 8);
                float4 v0 = p[0], v1 = p[1];
                float f[8] = {v0.x, v0.y, v0.z, v0.w, v1.x, v1.y, v1.z, v1.w};
                __nv_bfloat16 hb[8], lb[8];
                #pragma unroll
                for (int j = 0; j < 8; ++j) bsplit(f[j], hb[j], lb[j]);
                int o = r * 36 + q * 4;
                uint4 uh, ul;
                uh.x = pack2(hb[0], hb[1]); uh.y = pack2(hb[2], hb[3]);
                uh.z = pack2(hb[4], hb[5]); uh.w = pack2(hb[6], hb[7]);
                ul.x = pack2(lb[0], lb[1]); ul.y = pack2(lb[2], lb[3]);
                ul.z = pack2(lb[4], lb[5]); ul.w = pack2(lb[6], lb[7]);
                *(uint4*)(dh + o) = uh;
                *(uint4*)(dl + o) = ul;
            }
        }
        stage_B2(smem, SM_B, g_W1bh, g_W1bl, 384, 0, c, tid);
        __syncthreads();
        chunk_mma(sb + SM_X, sb + SM_X + CHB, sb + SM_B, sb + SM_B + CHB, acc, aoff, boff);
    }
    __syncthreads();
    // epilogue 1: y1 = gelu(D + hvc[node])
    {
        const float* hvc = (const float*)(smem + SM_HVC);
        int r1 = m0 + g, r2 = r1 + 8;                 // t=0 rows for h-index calc
        int h1a = (base + r1) / 48 - n0;
        int h2a = (base + r2) / 48 - n0;
        int r1b = r1 + 16, r2b = r2 + 16;
        int h1b = (base + r1b) / 48 - n0;
        int h2b = (base + r2b) / 48 - n0;
        // custom epi (node-dependent bias rows)
        unsigned* y = (unsigned*)(smem + SM_Y1);
        const int hh[2][2] = {{h1a, h2a}, {h1b, h2b}};
        #pragma unroll
        for (int t = 0; t < 2; ++t) {
            int rr1 = m0 + t * 16 + g, rr2 = rr1 + 8;
            const float* b0 = hvc + hh[t][0] * 128;
            const float* b1 = hvc + hh[t][1] * 128;
            #pragma unroll
            for (int u = 0; u < 8; ++u) {
                int n = nb0 + u * 8 + 2 * t4;
                const float* cc = acc + (t * 8 + u) * 4;
                float ya = gelu_erf(cc[0] + b0[n]);
                float yb = gelu_erf(cc[1] + b0[n + 1]);
                float yc = gelu_erf(cc[2] + b1[n]);
                float yd = gelu_erf(cc[3] + b1[n + 1]);
                __nv_bfloat16 ha, la, hb2, lb2, hc, lc, hd, ld;
                bsplit(ya, ha, la); bsplit(yb, hb2, lb2);
                bsplit(yc, hc, lc); bsplit(yd, hd, ld);
                int ch = n >> 6, col = (n & 63) >> 1;
                unsigned* yh = y + (2 * ch) * CHW;
                unsigned* yl = y + (2 * ch + 1) * CHW;
                yh[rr1 * 36 + col] = pack2(ha, hb2);
                yl[rr1 * 36 + col] = pack2(la, lb2);
                yh[rr2 * 36 + col] = pack2(hc, hd);
                yl[rr2 * 36 + col] = pack2(lc, ld);
            }
        }
    }
    #pragma unroll
    for (int i = 0; i < 64; ++i) acc[i] = 0.f;
    __syncthreads();

    // ---------- GEMM2: Y1 @ W2^T ----------
    for (int c = 0; c < 2; ++c) {
        stage_B2(smem, SM_B, g_W2h, g_W2l, 128, 0, c, tid);
        __syncthreads();
        chunk_mma(sb + SM_Y1 + (2 * c) * CHB, sb + SM_Y1 + (2 * c + 1) * CHB,
                  sb + SM_B, sb + SM_B + CHB, acc, aoff, boff);
        __syncthreads();
    }
    {
        const float* b2 = (const float*)(smem + SM_BIAS);
        epi_store(smem, SM_X, acc, b2, b2, m0, nb0, g, t4);
    }
    #pragma unroll
    for (int i = 0; i < 64; ++i) acc[i] = 0.f;
    __syncthreads();

    // ---------- GEMM3: Y2 @ W3^T ----------
    for (int c = 0; c < 2; ++c) {
        stage_B2(smem, SM_B, g_W3h, g_W3l, 128, 0, c, tid);
        __syncthreads();
        chunk_mma(sb + SM_X + (2 * c) * CHB, sb + SM_X + (2 * c + 1) * CHB,
                  sb + SM_B, sb + SM_B + CHB, acc, aoff, boff);
        __syncthreads();
    }
    // epilogue 3: msg*(mask) -> sMsg [n][129]; segment sums -> g_dh
    {
        const float* b3 = (const float*)(smem + SM_BIAS) + 128;
        float* sMsg = (float*)(smem + SM_Y1);
        #pragma unroll
        for (int t = 0; t < 2; ++t) {
            int r1 = m0 + t * 16 + g, r2 = r1 + 8;
            float mk1 = mask_attend[base + r1];
            float mk2 = mask_attend[base + r2];
            #pragma unroll
            for (int u = 0; u < 8; ++u) {
                int n = nb0 + u * 8 + 2 * t4;
                const float* cc = acc + (t * 8 + u) * 4;
                sMsg[n * 129 + r1]       = (cc[0] + b3[n])     * mk1;
                sMsg[(n + 1) * 129 + r1] = (cc[1] + b3[n + 1]) * mk1;
                sMsg[n * 129 + r2]       = (cc[2] + b3[n])     * mk2;
                sMsg[(n + 1) * 129 + r2] = (cc[3] + b3[n + 1]) * mk2;
            }
        }
    }
    __syncthreads();
    if (tid < 128) {
        const float* sMsg = (const float*)(smem + SM_Y1);
        int col = tid;
        #pragma unroll
        for (int gg = 0; gg < 4; ++gg) {
            int ng = n0 + gg;
            if (ng >= n_nodes) break;
            int lo = ng * 48 - base, hi = lo + 48;
            if (lo < 0) lo = 0;
            if (hi > 128) hi = 128;
            if (lo < hi) {
                float s = 0.f;
                for (int r = lo; r < hi; ++r) s += sMsg[col * 129 + r];
                atomicAdd(&g_dh[(size_t)ng * 128 + col], s);
            }
        }
    }
}

// node LN1 -> g_Hbuf
__global__ void __launch_bounds__(NT, 1)
node_ln_kernel(const float* __restrict__ h_V,
               const float* __restrict__ ln1_g, const float* __restrict__ ln1_b) {
    const int tid = threadIdx.x;
    const int lid = tid & 31;
    const int node = blockIdx.x * 8 + (tid >> 5);
    float4 dv = ((const float4*)(g_dh + (size_t)node * 128))[lid];
    float4 hv = ((const float4*)(h_V + (size_t)node * 128))[lid];
    float v0 = hv.x + dv.x * (1.0f / 30.0f);
    float v1 = hv.y + dv.y * (1.0f / 30.0f);
    float v2 = hv.z + dv.z * (1.0f / 30.0f);
    float v3 = hv.w + dv.w * (1.0f / 30.0f);
    float s = v0 + v1 + v2 + v3;
    float s2 = v0 * v0 + v1 * v1 + v2 * v2 + v3 * v3;
    #pragma unroll
    for (int off = 16; off > 0; off >>= 1) {
        s  += __shfl_xor_sync(0xffffffffu, s,  off);
        s2 += __shfl_xor_sync(0xffffffffu, s2, off);
    }
    float mean = s * (1.0f / 128.0f);
    float rstd = rsqrtf(s2 * (1.0f / 128.0f) - mean * mean + 1e-5f);
    float4 g = ((const float4*)ln1_g)[lid];
    float4 b = ((const float4*)ln1_b)[lid];
    float4 o;
    o.x = (v0 - mean) * rstd * g.x + b.x;
    o.y = (v1 - mean) * rstd * g.y + b.y;
    o.z = (v2 - mean) * rstd * g.z + b.z;
    o.w = (v3 - mean) * rstd * g.w + b.w;
    ((float4*)(g_Hbuf + (size_t)node * 128))[lid] = o;
}

// ---- FFN tensor-core kernel: 128 nodes per CTA ----
#define FM_H 0
#define FM_B (4 * CHB)
#define FM_F (6 * CHB)
#define FM_O (6 * CHB)            // fp32 [128][132], overlaps F after GEMM2
#define FM_TOT (10 * CHB)

__global__ void __launch_bounds__(NT, 1)
ffn_tc_kernel(const float* __restrict__ mask_V,
              const float* __restrict__ Win_b, const float* __restrict__ Wout_b,
              const float* __restrict__ ln2_g, const float* __restrict__ ln2_b,
              float* __restrict__ out)
{
    extern __shared__ char smem[];
    const int tid = threadIdx.x;
    const int wid = tid >> 5;
    const int lane = tid & 31;
    const int g = lane >> 2, t4 = lane & 3;
    const int wm = wid >> 1, wn = wid & 1;
    const int m0 = wm * 32, nb0 = wn * 64;
    const int nb = blockIdx.x * 128;
    const unsigned sb = (unsigned)__cvta_generic_to_shared(smem);

    const unsigned aoff = (m0 + (lane & 15)) * 144 + (lane >> 4) * 16;
    const unsigned boff = (nb0 + (lane & 7)) * 144 + (lane >> 3) * 16;

    // stage H chunks (fp32 -> bf16 hi/lo)
    for (int c = 0; c < 2; ++c) {
        unsigned* dh = (unsigned*)(smem + FM_H + 2 * c * CHB);
        unsigned* dl = dh + CHW;
        #pragma unroll
        for (int i = 0; i < 4; ++i) {
            int idx = i * NT + tid;
            int r = idx >> 3, q = idx & 7;
            const float4* p = (const float4*)(g_Hbuf + (size_t)(nb + r) * 128 + c * 64 + q * 8);
            float4 v0 = p[0], v1 = p[1];
            float f[8] = {v0.x, v0.y, v0.z, v0.w, v1.x, v1.y, v1.z, v1.w};
            __nv_bfloat16 hb[8], lb[8];
            #pragma unroll
            for (int j = 0; j < 8; ++j) bsplit(f[j], hb[j], lb[j]);
            int o = r * 36 + q * 4;
            uint4 uh, ul;
            uh.x = pack2(hb[0], hb[1]); uh.y = pack2(hb[2], hb[3]);
            uh.z = pack2(hb[4], hb[5]); uh.w = pack2(hb[6], hb[7]);
            ul.x = pack2(lb[0], lb[1]); ul.y = pack2(lb[2], lb[3]);
            ul.z = pack2(lb[4], lb[5]); ul.w = pack2(lb[6], lb[7]);
            *(uint4*)(dh + o) = uh;
            *(uint4*)(dl + o) = ul;
        }
    }

    float acc2[64];
    #pragma unroll
    for (int i = 0; i < 64; ++i) acc2[i] = 0.f;

    for (int nt = 0; nt < 4; ++nt) {
        float acc1[64];
        #pragma unroll
        for (int i = 0; i < 64; ++i) acc1[i] = 0.f;
        // GEMM1: H @ Win[nt*128..]^T
        for (int c = 0; c < 2; ++c) {
            __syncthreads();
            stage_B2(smem, FM_B, g_Winh, g_Winl, 128, nt * 128, c, tid);
            __syncthreads();
            chunk_mma(sb + FM_H + 2 * c * CHB, sb + FM_H + (2 * c + 1) * CHB,
                      sb + FM_B, sb + FM_B + CHB, acc1, aoff, boff);
        }
        __syncthreads();
        {
            const float* bin = Win_b + nt * 128;
            epi_store(smem, FM_F, acc1, bin, bin, m0, nb0, g, t4);
        }
        __syncthreads();
        // GEMM2 partial: F_nt @ Wout[:, nt*128..]^T
        for (int c = 0; c < 2; ++c) {
            stage_B2(smem, FM_B, g_Wouth, g_Woutl, 512, 0, nt * 2 + c, tid);
            __syncthreads();
            chunk_mma(sb + FM_F + 2 * c * CHB, sb + FM_F + (2 * c + 1) * CHB,
                      sb + FM_B, sb + FM_B + CHB, acc2, aoff, boff);
            __syncthreads();
        }
    }

    // epilogue: O = acc2 + bout -> smem fp32 [128][132]
    {
        float* O = (float*)(smem + FM_O);
        #pragma unroll
        for (int t = 0; t < 2; ++t) {
            int r1 = m0 + t * 16 + g, r2 = r1 + 8;
            #pragma unroll
            for (int u = 0; u < 8; ++u) {
                int n = nb0 + u * 8 + 2 * t4;
                const float* cc = acc2 + (t * 8 + u) * 4;
                float b0 = Wout_b[n], b1 = Wout_b[n + 1];
                O[r1 * 132 + n]     = cc[0] + b0;
                O[r1 * 132 + n + 1] = cc[1] + b1;
                O[r2 * 132 + n]     = cc[2] + b0;
                O[r2 * 132 + n + 1] = cc[3] + b1;
            }
        }
    }
    __syncthreads();

    // residual + LN2 + mask: each warp handles 16 rows
    {
        const float* O = (const float*)(smem + FM_O);
        for (int rr = 0; rr < 16; ++rr) {
            int r = wid * 16 + rr;
            float v[4];
            float s = 0.f, s2 = 0.f;
            #pragma unroll
            for (int i = 0; i < 4; ++i) {
                int n = lane + i * 32;
                v[i] = O[r * 132 + n] + g_Hbuf[(size_t)(nb + r) * 128 + n];
                s += v[i]; s2 += v[i] * v[i];
            }
            #pragma unroll
            for (int off = 16; off > 0; off >>= 1) {
                s  += __shfl_xor_sync(0xffffffffu, s,  off);
                s2 += __shfl_xor_sync(0xffffffffu, s2, off);
            }
            float mean = s * (1.0f / 128.0f);
            float rstd = rsqrtf(s2 * (1.0f / 128.0f) - mean * mean + 1e-5f);
            float mv = mask_V[nb + r];
            #pragma unroll
            for (int i = 0; i < 4; ++i) {
                int n = lane + i * 32;
                out[(size_t)(nb + r) * 128 + n] =
                    mv * ((v[i] - mean) * rstd * ln2_g[n] + ln2_b[n]);
            }
        }
    }
}

extern "C" void kernel_launch(void* const* d_in, const int* in_sizes, int n_in,
                              void* d_out, int out_size) {
    const float* h_V         = (const float*)d_in[0];
    const float* h_E         = (const float*)d_in[1];
    const float* mask_V      = (const float*)d_in[2];
    const float* mask_attend = (const float*)d_in[3];
    const float* W1_w        = (const float*)d_in[4];
    const float* W1_b        = (const float*)d_in[5];
    const float* W2_w        = (const float*)d_in[6];
    const float* W2_b        = (const float*)d_in[7];
    const float* W3_w        = (const float*)d_in[8];
    const float* W3_b        = (const float*)d_in[9];
    const float* ln1_g       = (const float*)d_in[10];
    const float* ln1_b       = (const float*)d_in[11];
    const float* ln2_g       = (const float*)d_in[12];
    const float* ln2_b       = (const float*)d_in[13];
    const float* Win_b       = (const float*)d_in[15];
    const float* Wout_b      = (const float*)d_in[17];
    const float* Win_w       = (const float*)d_in[14];
    const float* Wout_w      = (const float*)d_in[16];

    int nodes = in_sizes[0] / Hdim;        // 4096
    int tiles = (nodes * KNB + 127) / 128; // 1536

    prep_weights<<<832, 256>>>(W1_w, W2_w, W3_w, Win_w, Wout_w);

    cudaFuncSetAttribute(hvc_kernel, cudaFuncAttributeMaxDynamicSharedMemorySize, 73728);
    hvc_kernel<<<nodes / 8, NT, 73728>>>(h_V, W1_w, W1_b);

    cudaFuncSetAttribute(edge_gemm_kernel, cudaFuncAttributeMaxDynamicSharedMemorySize, SM_TOT);
    edge_gemm_kernel<<<tiles, NT, SM_TOT>>>(h_E, mask_attend, W2_b, W3_b, nodes);

    node_ln_kernel<<<nodes / 8, NT>>>(h_V, ln1_g, ln1_b);

    cudaFuncSetAttribute(ffn_tc_kernel, cudaFuncAttributeMaxDynamicSharedMemorySize, FM_TOT);
    ffn_tc_kernel<<<nodes / 128, NT, FM_TOT>>>(mask_V, Win_b, Wout_b, ln2_g, ln2_b, (float*)d_out);
}

// round 14
// speedup vs baseline: 1.0570x; 1.0570x over previous
#include <cuda_runtime.h>
#include <cuda_bf16.h>
#include <math.h>

#define Hdim 128
#define KNB  48
#define NT   256
typedef unsigned long long u64;

__device__ __nv_bfloat16 g_W1bh[128 * 384];   // [n][k] hi
__device__ __nv_bfloat16 g_W1bl[128 * 384];
__device__ __nv_bfloat16 g_W2h[128 * 128];
__device__ __nv_bfloat16 g_W2l[128 * 128];
__device__ __nv_bfloat16 g_W3h[128 * 128];
__device__ __nv_bfloat16 g_W3l[128 * 128];
__device__ float2 g_Winp[64 * 512];
__device__ float2 g_Woutp[256 * 128];
__device__ float  g_hvc[4096 * 128];
__device__ float  g_dh[4096 * 128];
__device__ float  g_Hbuf[4096 * 128];

__device__ __forceinline__ float gelu_erf(float x) {
    return 0.5f * x * (1.0f + erff(x * 0.70710678118654752440f));
}
__device__ __forceinline__ void fma2(u64& d, u64 a, u64 b) {
    asm("fma.rn.f32x2 %0, %1, %2, %0;" : "+l"(d) : "l"(a), "l"(b));
}
__device__ __forceinline__ void lds2(u64& a, u64& b, unsigned addr) {
    asm volatile("ld.shared.v2.b64 {%0,%1}, [%2];" : "=l"(a), "=l"(b) : "r"(addr));
}
__device__ __forceinline__ float hadd(u64 p) {
    float lo, hi;
    asm("mov.b64 {%0,%1}, %2;" : "=f"(lo), "=f"(hi) : "l"(p));
    return lo + hi;
}
__device__ __forceinline__ unsigned pack2(__nv_bfloat16 a, __nv_bfloat16 b) {
    return ((unsigned)__bfloat16_as_ushort(b) << 16) | (unsigned)__bfloat16_as_ushort(a);
}
__device__ __forceinline__ void bsplit(float x, __nv_bfloat16& h, __nv_bfloat16& l) {
    h = __float2bfloat16_rn(x);
    l = __float2bfloat16_rn(x - __bfloat162float(h));
}
__device__ __forceinline__ void mma16816(float* c, const unsigned* a, const unsigned* b) {
    asm volatile(
        "mma.sync.aligned.m16n8k16.row.col.f32.bf16.bf16.f32 "
        "{%0,%1,%2,%3}, {%4,%5,%6,%7}, {%8,%9}, {%0,%1,%2,%3};"
        : "+f"(c[0]), "+f"(c[1]), "+f"(c[2]), "+f"(c[3])
        : "r"(a[0]), "r"(a[1]), "r"(a[2]), "r"(a[3]), "r"(b[0]), "r"(b[1]));
}
__device__ __forceinline__ void ldsm4(unsigned* r, unsigned addr) {
    asm volatile("ldmatrix.sync.aligned.m8n8.x4.shared.b16 {%0,%1,%2,%3}, [%4];"
        : "=r"(r[0]), "=r"(r[1]), "=r"(r[2]), "=r"(r[3]) : "r"(addr));
}
__device__ __forceinline__ void cpa16(unsigned dst, const void* src) {
    asm volatile("cp.async.ca.shared.global [%0], [%1], 16;" :: "r"(dst), "l"(src));
}
#define CP_COMMIT() asm volatile("cp.async.commit_group;" ::: "memory")
#define CP_WAIT0()  asm volatile("cp.async.wait_group 0;" ::: "memory")

__global__ void prep_weights(const float* __restrict__ W1_w, const float* __restrict__ W2_w,
                             const float* __restrict__ W3_w, const float* __restrict__ Win_w,
                             const float* __restrict__ Wout_w) {
    int idx = blockIdx.x * blockDim.x + threadIdx.x;
    __nv_bfloat16 h, l;
    if (idx < 49152) {
        int n = idx / 384, k = idx % 384;
        bsplit(W1_w[n * 512 + 128 + k], h, l);
        g_W1bh[idx] = h; g_W1bl[idx] = l;
    } else if (idx < 65536) {
        int i = idx - 49152;
        bsplit(W2_w[i], h, l);
        g_W2h[i] = h; g_W2l[i] = l;
    } else if (idx < 81920) {
        int i = idx - 65536;
        bsplit(W3_w[i], h, l);
        g_W3h[i] = h; g_W3l[i] = l;
    } else if (idx < 114688) {
        int i = idx - 81920;
        int k2 = i >> 9, f = i & 511;
        g_Winp[i] = make_float2(Win_w[f * 128 + 2 * k2], Win_w[f * 128 + 2 * k2 + 1]);
    } else if (idx < 147456) {
        int i = idx - 114688;
        int k2 = i >> 7, n = i & 127;
        g_Woutp[i] = make_float2(Wout_w[n * 512 + 2 * k2], Wout_w[n * 512 + 2 * k2 + 1]);
    }
}

// hvc = h_V @ W1a^T + b1 (exact fp32); also zero g_dh
__global__ void __launch_bounds__(NT, 1)
hvc_kernel(const float* __restrict__ h_V, const float* __restrict__ W1_w,
           const float* __restrict__ W1_b) {
    extern __shared__ float smh[];
    float* sW  = smh;
    float* sHv = smh + 16384;
    const int tid = threadIdx.x;
    const int nb  = blockIdx.x * 8;
    #pragma unroll
    for (int i = 0; i < 16; ++i) {
        int id4 = i * NT + tid;
        int k4 = id4 >> 7, n = id4 & 127;
        float4 v = ((const float4*)(W1_w + (size_t)n * 512))[k4];
        sW[(4 * k4 + 0) * 128 + n] = v.x;
        sW[(4 * k4 + 1) * 128 + n] = v.y;
        sW[(4 * k4 + 2) * 128 + n] = v.z;
        sW[(4 * k4 + 3) * 128 + n] = v.w;
    }
    {
        int node = tid >> 5, q = tid & 31;
        float4 v = ((const float4*)(h_V + (size_t)(nb + node) * 128))[q];
        *(float4*)(sHv + node * 128 + 4 * q) = v;
        ((float4*)(g_dh + (size_t)nb * 128))[tid] = make_float4(0.f, 0.f, 0.f, 0.f);
    }
    __syncthreads();
    #pragma unroll
    for (int it = 0; it < 4; ++it) {
        int o = it * NT + tid;
        int node = o >> 7, col = o & 127;
        const float* hv = sHv + node * 128;
        float a = W1_b[col];
        #pragma unroll 8
        for (int k = 0; k < 128; ++k) a = fmaf(hv[k], sW[k * 128 + col], a);
        g_hvc[(size_t)(nb + node) * 128 + col] = a;
    }
}

#define CHB 18432
#define CHW (CHB / 4)

// async-stage one 64k B chunk (h,l) from prepped bf16 [n][K]
__device__ __forceinline__ void stage_B_async(unsigned dsth, const __nv_bfloat16* gh,
                                              const __nv_bfloat16* gl, int K, int rowoff,
                                              int c, int tid) {
    #pragma unroll
    for (int i = 0; i < 4; ++i) {
        int idx = i * NT + tid;
        int n = idx >> 3, q = idx & 7;
        unsigned d = dsth + n * 144 + q * 16;
        cpa16(d,       gh + (size_t)(rowoff + n) * K + c * 64 + q * 8);
        cpa16(d + CHB, gl + (size_t)(rowoff + n) * K + c * 64 + q * 8);
    }
}

// one 64k chunk: acc[64] += A(128x64) * B^T, split-bf16 (hh+hl+lh)
__device__ __forceinline__ void chunk_mma(unsigned sAh, unsigned sAl,
                                          unsigned sBh, unsigned sBl,
                                          float* acc, unsigned aoff, unsigned boff) {
    #pragma unroll
    for (int v = 0; v < 2; ++v) {
        unsigned ah[2][2][4], al[2][2][4];
        #pragma unroll
        for (int t = 0; t < 2; ++t)
            #pragma unroll
            for (int sl = 0; sl < 2; ++sl) {
                unsigned off = aoff + t * 2304 + (2 * v + sl) * 32;
                ldsm4(ah[t][sl], sAh + off);
                ldsm4(al[t][sl], sAl + off);
            }
        #pragma unroll
        for (int u = 0; u < 8; ++u) {
            unsigned bh4[4], bl4[4];
            unsigned off = boff + u * 1152 + v * 64;
            ldsm4(bh4, sBh + off);
            ldsm4(bl4, sBl + off);
            #pragma unroll
            for (int t = 0; t < 2; ++t) {
                float* cc = acc + (t * 8 + u) * 4;
                #pragma unroll
                for (int sl = 0; sl < 2; ++sl) {
                    mma16816(cc, ah[t][sl], bh4 + 2 * sl);
                    mma16816(cc, ah[t][sl], bl4 + 2 * sl);
                    mma16816(cc, al[t][sl], bh4 + 2 * sl);
                }
            }
        }
    }
}

// write acc (bias-added, gelu'd) into bf16 hi/lo chunks at smem byte base sm_y
__device__ __forceinline__ void epi_store(char* smem, int sm_y, const float* acc,
                                          const float* badd0, const float* badd1,
                                          int m0, int nb0, int g, int t4) {
    unsigned* y = (unsigned*)(smem + sm_y);
    #pragma unroll
    for (int t = 0; t < 2; ++t) {
        int r1 = m0 + t * 16 + g, r2 = r1 + 8;
        #pragma unroll
        for (int u = 0; u < 8; ++u) {
            int n = nb0 + u * 8 + 2 * t4;
            const float* cc = acc + (t * 8 + u) * 4;
            float ya = gelu_erf(cc[0] + badd0[n]);
            float yb = gelu_erf(cc[1] + badd0[n + 1]);
            float yc = gelu_erf(cc[2] + badd1[n]);
            float yd = gelu_erf(cc[3] + badd1[n + 1]);
            __nv_bfloat16 ha, la, hb, lb, hc, lc, hd, ld;
            bsplit(ya, ha, la); bsplit(yb, hb, lb);
            bsplit(yc, hc, lc); bsplit(yd, hd, ld);
            int ch = n >> 6, col = (n & 63) >> 1;
            unsigned* yh = y + (2 * ch) * CHW;
            unsigned* yl = y + (2 * ch + 1) * CHW;
            yh[r1 * 36 + col] = pack2(ha, hb);
            yl[r1 * 36 + col] = pack2(la, lb);
            yh[r2 * 36 + col] = pack2(hc, hd);
            yl[r2 * 36 + col] = pack2(lc, ld);
        }
    }
}

// ---- edge GEMM smem layout (bytes) ----
#define SM_BIAS 0
#define SM_HVC  1024
#define SM_Y1   3072                    // 4 chunks
#define SM_X    (SM_Y1 + 4 * CHB)       // A double-buffer (2x h/l); later Y2
#define SM_B    (SM_X + 4 * CHB)        // B double-buffer (2x h/l)
#define SM_TOT  (SM_B + 4 * CHB)        // 224256

__global__ void __launch_bounds__(NT, 1)
edge_gemm_kernel(const float* __restrict__ h_E, const float* __restrict__ mask_attend,
                 const float* __restrict__ W2_b, const float* __restrict__ W3_b,
                 int n_nodes) {
    extern __shared__ char smem[];
    const int tid = threadIdx.x;
    const int lane = tid & 31;
    const int wid = tid >> 5;
    const int g = lane >> 2, t4 = lane & 3;
    const int wm = wid >> 1, wn = wid & 1;
    const int m0 = wm * 32, nb0 = wn * 64;
    const int base = blockIdx.x * 128;
    const int n0 = base / 48;
    const unsigned sb = (unsigned)__cvta_generic_to_shared(smem);

    const unsigned aoff = (m0 + (lane & 15)) * 144 + (lane >> 4) * 16;
    const unsigned boff = (nb0 + (lane & 7)) * 144 + (lane >> 3) * 16;

    // per-thread A staging coords
    const int ar = tid >> 3, aq = tid & 7;     // handles rows ar, ar+32, ar+64, ar+96
    const float* heb = h_E + (size_t)base * 384 + aq * 8;

    if (tid < 128) {
        ((float*)(smem + SM_BIAS))[tid]       = W2_b[tid];
        ((float*)(smem + SM_BIAS))[128 + tid] = W3_b[tid];
    }
    for (int t = tid; t < 512; t += NT) {
        int gg = t >> 7, c = t & 127;
        int nd = n0 + gg;
        ((float*)(smem + SM_HVC))[t] = (nd < n_nodes) ? g_hvc[(size_t)nd * 128 + c] : 0.f;
    }

    float acc[64];
    #pragma unroll
    for (int i = 0; i < 64; ++i) acc[i] = 0.f;

    float4 ar0[2], ar1[2], ar2[2], ar3[2];

    // load A chunk floats for column-chunk c into registers
    #define LOADA(c)                                                          \
      { const float4* p0 = (const float4*)(heb + (size_t)(ar)      * 384 + (c) * 64); \
        const float4* p1 = (const float4*)(heb + (size_t)(ar + 32) * 384 + (c) * 64); \
        const float4* p2 = (const float4*)(heb + (size_t)(ar + 64) * 384 + (c) * 64); \
        const float4* p3 = (const float4*)(heb + (size_t)(ar + 96) * 384 + (c) * 64); \
        ar0[0] = p0[0]; ar0[1] = p0[1]; ar1[0] = p1[0]; ar1[1] = p1[1];       \
        ar2[0] = p2[0]; ar2[1] = p2[1]; ar3[0] = p3[0]; ar3[1] = p3[1]; }

    // convert + store registers into A buffer (h at dst, l at dst+CHB)
    #define STOREA(dstb)                                                      \
      { unsigned* dh = (unsigned*)(smem + (dstb));                            \
        unsigned* dl = dh + CHW;                                              \
        float4* rr[4][2] = {{&ar0[0],&ar0[1]},{&ar1[0],&ar1[1]},              \
                            {&ar2[0],&ar2[1]},{&ar3[0],&ar3[1]}};             \
        _Pragma("unroll")                                                     \
        for (int i = 0; i < 4; ++i) {                                         \
            float f[8] = {rr[i][0]->x, rr[i][0]->y, rr[i][0]->z, rr[i][0]->w, \
                          rr[i][1]->x, rr[i][1]->y, rr[i][1]->z, rr[i][1]->w};\
            __nv_bfloat16 hb[8], lb[8];                                       \
            _Pragma("unroll")                                                 \
            for (int j = 0; j < 8; ++j) bsplit(f[j], hb[j], lb[j]);           \
            int o = (ar + i * 32) * 36 + aq * 4;                              \
            uint4 uh, ul;                                                     \
            uh.x = pack2(hb[0], hb[1]); uh.y = pack2(hb[2], hb[3]);           \
            uh.z = pack2(hb[4], hb[5]); uh.w = pack2(hb[6], hb[7]);           \
            ul.x = pack2(lb[0], lb[1]); ul.y = pack2(lb[2], lb[3]);           \
            ul.z = pack2(lb[4], lb[5]); ul.w = pack2(lb[6], lb[7]);           \
            *(uint4*)(dh + o) = uh;                                           \
            *(uint4*)(dl + o) = ul;                                           \
        } }

    // ---------- GEMM1: h_E @ W1b^T, K=384, double-buffered pipeline ----------
    stage_B_async(sb + SM_B, g_W1bh, g_W1bl, 384, 0, 0, tid);
    CP_COMMIT();
    LOADA(0);
    STOREA(SM_X);
    CP_WAIT0();
    __syncthreads();
    for (int c = 0; c < 6; ++c) {
        const int cur = c & 1, nxt = cur ^ 1;
        if (c < 5) {
            stage_B_async(sb + SM_B + nxt * 2 * CHB, g_W1bh, g_W1bl, 384, 0, c + 1, tid);
            CP_COMMIT();
            LOADA(c + 1);
        }
        chunk_mma(sb + SM_X + cur * 2 * CHB, sb + SM_X + cur * 2 * CHB + CHB,
                  sb + SM_B + cur * 2 * CHB, sb + SM_B + cur * 2 * CHB + CHB,
                  acc, aoff, boff);
        if (c < 5) STOREA(SM_X + nxt * 2 * CHB);
        CP_WAIT0();
        __syncthreads();
    }

    // prefetch ALL of W2 (both k-chunks) into the 4 B buffers
    stage_B_async(sb + SM_B,           g_W2h, g_W2l, 128, 0, 0, tid);
    stage_B_async(sb + SM_B + 2 * CHB, g_W2h, g_W2l, 128, 0, 1, tid);
    CP_COMMIT();

    // epilogue 1: y1 = gelu(D + hvc[node]) -> Y1 chunks
    {
        const float* hvc = (const float*)(smem + SM_HVC);
        unsigned* y = (unsigned*)(smem + SM_Y1);
        #pragma unroll
        for (int t = 0; t < 2; ++t) {
            int rr1 = m0 + t * 16 + g, rr2 = rr1 + 8;
            const float* b0 = hvc + ((base + rr1) / 48 - n0) * 128;
            const float* b1 = hvc + ((base + rr2) / 48 - n0) * 128;
            #pragma unroll
            for (int u = 0; u < 8; ++u) {
                int n = nb0 + u * 8 + 2 * t4;
                const float* cc = acc + (t * 8 + u) * 4;
                float ya = gelu_erf(cc[0] + b0[n]);
                float yb = gelu_erf(cc[1] + b0[n + 1]);
                float yc = gelu_erf(cc[2] + b1[n]);
                float yd = gelu_erf(cc[3] + b1[n + 1]);
                __nv_bfloat16 ha, la, hb2, lb2, hc, lc, hd, ld;
                bsplit(ya, ha, la); bsplit(yb, hb2, lb2);
                bsplit(yc, hc, lc); bsplit(yd, hd, ld);
                int ch = n >> 6, col = (n & 63) >> 1;
                unsigned* yh = y + (2 * ch) * CHW;
                unsigned* yl = y + (2 * ch + 1) * CHW;
                yh[rr1 * 36 + col] = pack2(ha, hb2);
                yl[rr1 * 36 + col] = pack2(la, lb2);
                yh[rr2 * 36 + col] = pack2(hc, hd);
                yl[rr2 * 36 + col] = pack2(lc, ld);
            }
        }
    }
    #pragma unroll
    for (int i = 0; i < 64; ++i) acc[i] = 0.f;
    CP_WAIT0();
    __syncthreads();

    // ---------- GEMM2: Y1 @ W2^T (W2 fully resident) ----------
    chunk_mma(sb + SM_Y1,           sb + SM_Y1 + CHB,
              sb + SM_B,            sb + SM_B + CHB,            acc, aoff, boff);
    chunk_mma(sb + SM_Y1 + 2 * CHB, sb + SM_Y1 + 3 * CHB,
              sb + SM_B + 2 * CHB,  sb + SM_B + 3 * CHB,        acc, aoff, boff);
    __syncthreads();

    // prefetch ALL of W3, overlapped with epilogue 2
    stage_B_async(sb + SM_B,           g_W3h, g_W3l, 128, 0, 0, tid);
    stage_B_async(sb + SM_B + 2 * CHB, g_W3h, g_W3l, 128, 0, 1, tid);
    CP_COMMIT();
    {
        const float* b2 = (const float*)(smem + SM_BIAS);
        epi_store(smem, SM_X, acc, b2, b2, m0, nb0, g, t4);
    }
    #pragma unroll
    for (int i = 0; i < 64; ++i) acc[i] = 0.f;
    CP_WAIT0();
    __syncthreads();

    // ---------- GEMM3: Y2 @ W3^T ----------
    chunk_mma(sb + SM_X,           sb + SM_X + CHB,
              sb + SM_B,           sb + SM_B + CHB,             acc, aoff, boff);
    chunk_mma(sb + SM_X + 2 * CHB, sb + SM_X + 3 * CHB,
              sb + SM_B + 2 * CHB, sb + SM_B + 3 * CHB,         acc, aoff, boff);
    __syncthreads();

    // epilogue 3: msg*(mask) -> sMsg [n][129]; segment sums -> g_dh
    {
        const float* b3 = (const float*)(smem + SM_BIAS) + 128;
        float* sMsg = (float*)(smem + SM_Y1);
        #pragma unroll
        for (int t = 0; t < 2; ++t) {
            int r1 = m0 + t * 16 + g, r2 = r1 + 8;
            float mk1 = mask_attend[base + r1];
            float mk2 = mask_attend[base + r2];
            #pragma unroll
            for (int u = 0; u < 8; ++u) {
                int n = nb0 + u * 8 + 2 * t4;
                const float* cc = acc + (t * 8 + u) * 4;
                sMsg[n * 129 + r1]       = (cc[0] + b3[n])     * mk1;
                sMsg[(n + 1) * 129 + r1] = (cc[1] + b3[n + 1]) * mk1;
                sMsg[n * 129 + r2]       = (cc[2] + b3[n])     * mk2;
                sMsg[(n + 1) * 129 + r2] = (cc[3] + b3[n + 1]) * mk2;
            }
        }
    }
    __syncthreads();
    if (tid < 128) {
        const float* sMsg = (const float*)(smem + SM_Y1);
        int col = tid;
        #pragma unroll
        for (int gg = 0; gg < 4; ++gg) {
            int ng = n0 + gg;
            if (ng >= n_nodes) break;
            int lo = ng * 48 - base, hi = lo + 48;
            if (lo < 0) lo = 0;
            if (hi > 128) hi = 128;
            if (lo < hi) {
                float s = 0.f;
                for (int r = lo; r < hi; ++r) s += sMsg[col * 129 + r];
                atomicAdd(&g_dh[(size_t)ng * 128 + col], s);
            }
        }
    }
}

// node LN1 -> g_Hbuf
__global__ void __launch_bounds__(NT, 1)
node_ln_kernel(const float* __restrict__ h_V,
               const float* __restrict__ ln1_g, const float* __restrict__ ln1_b) {
    const int tid = threadIdx.x;
    const int lid = tid & 31;
    const int node = blockIdx.x * 8 + (tid >> 5);
    float4 dv = ((const float4*)(g_dh + (size_t)node * 128))[lid];
    float4 hv = ((const float4*)(h_V + (size_t)node * 128))[lid];
    float v0 = hv.x + dv.x * (1.0f / 30.0f);
    float v1 = hv.y + dv.y * (1.0f / 30.0f);
    float v2 = hv.z + dv.z * (1.0f / 30.0f);
    float v3 = hv.w + dv.w * (1.0f / 30.0f);
    float s = v0 + v1 + v2 + v3;
    float s2 = v0 * v0 + v1 * v1 + v2 * v2 + v3 * v3;
    #pragma unroll
    for (int off = 16; off > 0; off >>= 1) {
        s  += __shfl_xor_sync(0xffffffffu, s,  off);
        s2 += __shfl_xor_sync(0xffffffffu, s2, off);
    }
    float mean = s * (1.0f / 128.0f);
    float rstd = rsqrtf(s2 * (1.0f / 128.0f) - mean * mean + 1e-5f);
    float4 g = ((const float4*)ln1_g)[lid];
    float4 b = ((const float4*)ln1_b)[lid];
    float4 o;
    o.x = (v0 - mean) * rstd * g.x + b.x;
    o.y = (v1 - mean) * rstd * g.y + b.y;
    o.z = (v2 - mean) * rstd * g.z + b.z;
    o.w = (v3 - mean) * rstd * g.w + b.w;
    ((float4*)(g_Hbuf + (size_t)node * 128))[lid] = o;
}

// ---- FFN (proven fp32 f32x2, round-12 version) ----
#define K2_H   0
#define K2_F   4096
#define K2_O   20480
#define SM2_BYTES  (24576 * 4)
#define INNERG(J, XB, XSTRIDE, WP, WROWF)                              \
  {                                                                    \
    ulonglong2 va = __ldg((const ulonglong2*)(WP));                    \
    ulonglong2 vb = __ldg((const ulonglong2*)((WP) + (WROWF)));        \
    _Pragma("unroll")                                                  \
    for (int j = 0; j < (J); ++j) {                                    \
      u64 xa, xb; lds2(xa, xb, (XB) + j * (XSTRIDE));                  \
      fma2(acc[j][0], xa, va.x); fma2(acc[j][1], xa, va.y);            \
      fma2(acc[j][0], xb, vb.x); fma2(acc[j][1], xb, vb.y);            \
    }                                                                  \
  }

__global__ void __launch_bounds__(NT, 1)
ffn_kernel(const float* __restrict__ mask_V,
           const float* __restrict__ Win_b, const float* __restrict__ Wout_b,
           const float* __restrict__ ln2_g, const float* __restrict__ ln2_b,
           float* __restrict__ out)
{
    extern __shared__ float smf[];
    const int tid = threadIdx.x;
    const int tx  = tid & 31;
    const int ty  = tid >> 5;
    const int wm  = ty >> 1;
    const int wn  = ty & 1;
    const int m0  = wm * 8;
    const int n0  = wn * 64 + 2 * tx;
    const int nb  = blockIdx.x * 32;

    const unsigned sbase = (unsigned)__cvta_generic_to_shared(smf);
    float* sH = smf + K2_H;
    float* sF = smf + K2_F;
    float* sO = smf + K2_O;
    const float* gWin  = (const float*)g_Winp;
    const float* gWout = (const float*)g_Woutp + 2 * n0;

    {
        const float4* src = (const float4*)(g_Hbuf + (size_t)nb * Hdim);
        float4* dst = (float4*)sH;
        #pragma unroll
        for (int i = 0; i < 4; ++i) dst[i * NT + tid] = src[i * NT + tid];
    }
    __syncthreads();

    u64 acc[8][2];
    for (int nblk = 0; nblk < 4; ++nblk) {
        #pragma unroll
        for (int j = 0; j < 8; ++j) { acc[j][0] = 0ULL; acc[j][1] = 0ULL; }
        {
            const unsigned xrow = sbase + K2_H * 4 + m0 * 512;
            const float* wp = gWin + nblk * 256 + 2 * n0;
            #pragma unroll 4
            for (int it = 0; it < 32; ++it)
                INNERG(8, xrow + it * 16, 512, wp + it * 2048, 1024);
        }
        float2 bv = *(const float2*)(Win_b + nblk * 128 + n0);
        #pragma unroll
        for (int j = 0; j < 8; ++j) {
            float2 r;
            r.x = gelu_erf(hadd(acc[j][0]) + bv.x);
            r.y = gelu_erf(hadd(acc[j][1]) + bv.y);
            *(float2*)(sF + (m0 + j) * 512 + nblk * 128 + n0) = r;
        }
    }
    __syncthreads();

    #pragma unroll
    for (int j = 0; j < 8; ++j) { acc[j][0] = 0ULL; acc[j][1] = 0ULL; }
    for (int kt = 0; kt < 4; ++kt) {
        const unsigned xrow = sbase + K2_F * 4 + m0 * 2048;
        const float* wp = gWout + kt * 16384;
        #pragma unroll 4
        for (int it = 0; it < 32; ++it)
            INNERG(8, xrow + kt * 512 + it * 16, 2048, wp + it * 512, 256);
    }
    {
        float2 bv = *(const float2*)(Wout_b + n0);
        #pragma unroll
        for (int j = 0; j < 8; ++j) {
            float2 r;
            r.x = hadd(acc[j][0]) + bv.x;
            r.y = hadd(acc[j][1]) + bv.y;
            *(float2*)(sO + (m0 + j) * 128 + n0) = r;
        }
    }
    __syncthreads();

    #pragma unroll
    for (int rr = 0; rr < 4; ++rr) {
        int r = ty + rr * 8;
        float v[4];
        float s = 0.f, s2 = 0.f;
        #pragma unroll
        for (int i = 0; i < 4; ++i) {
            int n = tx + i * 32;
            v[i] = sH[r * 128 + n] + sO[r * 128 + n];
            s += v[i]; s2 += v[i] * v[i];
        }
        #pragma unroll
        for (int off = 16; off > 0; off >>= 1) {
            s  += __shfl_xor_sync(0xffffffffu, s,  off);
            s2 += __shfl_xor_sync(0xffffffffu, s2, off);
        }
        float mean = s * (1.0f / 128.0f);
        float rstd = rsqrtf(s2 * (1.0f / 128.0f) - mean * mean + 1e-5f);
        float mv = mask_V[nb + r];
        #pragma unroll
        for (int i = 0; i < 4; ++i) {
            int n = tx + i * 32;
            out[(size_t)(nb + r) * Hdim + n] =
                mv * ((v[i] - mean) * rstd * ln2_g[n] + ln2_b[n]);
        }
    }
}

extern "C" void kernel_launch(void* const* d_in, const int* in_sizes, int n_in,
                              void* d_out, int out_size) {
    const float* h_V         = (const float*)d_in[0];
    const float* h_E         = (const float*)d_in[1];
    const float* mask_V      = (const float*)d_in[2];
    const float* mask_attend = (const float*)d_in[3];
    const float* W1_w        = (const float*)d_in[4];
    const float* W1_b        = (const float*)d_in[5];
    const float* W2_w        = (const float*)d_in[6];
    const float* W2_b        = (const float*)d_in[7];
    const float* W3_w        = (const float*)d_in[8];
    const float* W3_b        = (const float*)d_in[9];
    const float* ln1_g       = (const float*)d_in[10];
    const float* ln1_b       = (const float*)d_in[11];
    const float* ln2_g       = (const float*)d_in[12];
    const float* ln2_b       = (const float*)d_in[13];
    const float* Win_w       = (const float*)d_in[14];
    const float* Win_b       = (const float*)d_in[15];
    const float* Wout_w      = (const float*)d_in[16];
    const float* Wout_b      = (const float*)d_in[17];

    int nodes = in_sizes[0] / Hdim;        // 4096
    int tiles = (nodes * KNB + 127) / 128; // 1536

    prep_weights<<<576, 256>>>(W1_w, W2_w, W3_w, Win_w, Wout_w);

    cudaFuncSetAttribute(hvc_kernel, cudaFuncAttributeMaxDynamicSharedMemorySize, 73728);
    hvc_kernel<<<nodes / 8, NT, 73728>>>(h_V, W1_w, W1_b);

    cudaFuncSetAttribute(edge_gemm_kernel, cudaFuncAttributeMaxDynamicSharedMemorySize, SM_TOT);
    edge_gemm_kernel<<<tiles, NT, SM_TOT>>>(h_E, mask_attend, W2_b, W3_b, nodes);

    node_ln_kernel<<<nodes / 8, NT>>>(h_V, ln1_g, ln1_b);

    cudaFuncSetAttribute(ffn_kernel, cudaFuncAttributeMaxDynamicSharedMemorySize, SM2_BYTES);
    ffn_kernel<<<nodes / 32, NT, SM2_BYTES>>>(mask_V, Win_b, Wout_b, ln2_g, ln2_b, (float*)d_out);
}

// round 15
// speedup vs baseline: 1.4666x; 1.3876x over previous
#include <cuda_runtime.h>
#include <cuda_bf16.h>
#include <math.h>

#define Hdim 128
#define KNB  48
#define NT   256
typedef unsigned long long u64;

__device__ __nv_bfloat16 g_W1bh[128 * 384];   // [n][k] hi
__device__ __nv_bfloat16 g_W1bl[128 * 384];
__device__ __nv_bfloat16 g_W2h[128 * 128];
__device__ __nv_bfloat16 g_W2l[128 * 128];
__device__ __nv_bfloat16 g_W3h[128 * 128];
__device__ __nv_bfloat16 g_W3l[128 * 128];
__device__ float2 g_Winp[64 * 512];
__device__ float2 g_Woutp[256 * 128];
__device__ float  g_hvc[4096 * 128];
__device__ float  g_dh[4096 * 128];
__device__ float  g_Hbuf[4096 * 128];

__device__ __forceinline__ float gelu_erf(float x) {
    return 0.5f * x * (1.0f + erff(x * 0.70710678118654752440f));
}
__device__ __forceinline__ void fma2(u64& d, u64 a, u64 b) {
    asm("fma.rn.f32x2 %0, %1, %2, %0;" : "+l"(d) : "l"(a), "l"(b));
}
__device__ __forceinline__ void lds2(u64& a, u64& b, unsigned addr) {
    asm volatile("ld.shared.v2.b64 {%0,%1}, [%2];" : "=l"(a), "=l"(b) : "r"(addr));
}
__device__ __forceinline__ float hadd(u64 p) {
    float lo, hi;
    asm("mov.b64 {%0,%1}, %2;" : "=f"(lo), "=f"(hi) : "l"(p));
    return lo + hi;
}
__device__ __forceinline__ unsigned pack2(__nv_bfloat16 a, __nv_bfloat16 b) {
    return ((unsigned)__bfloat16_as_ushort(b) << 16) | (unsigned)__bfloat16_as_ushort(a);
}
__device__ __forceinline__ void bsplit(float x, __nv_bfloat16& h, __nv_bfloat16& l) {
    h = __float2bfloat16_rn(x);
    l = __float2bfloat16_rn(x - __bfloat162float(h));
}
__device__ __forceinline__ void mma16816(float* c, const unsigned* a, const unsigned* b) {
    asm volatile(
        "mma.sync.aligned.m16n8k16.row.col.f32.bf16.bf16.f32 "
        "{%0,%1,%2,%3}, {%4,%5,%6,%7}, {%8,%9}, {%0,%1,%2,%3};"
        : "+f"(c[0]), "+f"(c[1]), "+f"(c[2]), "+f"(c[3])
        : "r"(a[0]), "r"(a[1]), "r"(a[2]), "r"(a[3]), "r"(b[0]), "r"(b[1]));
}
__device__ __forceinline__ void ldsm4(unsigned* r, unsigned addr) {
    asm volatile("ldmatrix.sync.aligned.m8n8.x4.shared.b16 {%0,%1,%2,%3}, [%4];"
        : "=r"(r[0]), "=r"(r[1]), "=r"(r[2]), "=r"(r[3]) : "r"(addr));
}
__device__ __forceinline__ void cpa16(unsigned dst, const void* src) {
    asm volatile("cp.async.ca.shared.global [%0], [%1], 16;" :: "r"(dst), "l"(src));
}
#define CP_COMMIT() asm volatile("cp.async.commit_group;" ::: "memory")
#define CP_WAIT0()  asm volatile("cp.async.wait_group 0;" ::: "memory")

__global__ void prep_weights(const float* __restrict__ W1_w, const float* __restrict__ W2_w,
                             const float* __restrict__ W3_w, const float* __restrict__ Win_w,
                             const float* __restrict__ Wout_w) {
    int idx = blockIdx.x * blockDim.x + threadIdx.x;
    __nv_bfloat16 h, l;
    if (idx < 49152) {
        int n = idx / 384, k = idx % 384;
        bsplit(W1_w[n * 512 + 128 + k], h, l);
        g_W1bh[idx] = h; g_W1bl[idx] = l;
    } else if (idx < 65536) {
        int i = idx - 49152;
        bsplit(W2_w[i], h, l);
        g_W2h[i] = h; g_W2l[i] = l;
    } else if (idx < 81920) {
        int i = idx - 65536;
        bsplit(W3_w[i], h, l);
        g_W3h[i] = h; g_W3l[i] = l;
    } else if (idx < 114688) {
        int i = idx - 81920;
        int k2 = i >> 9, f = i & 511;
        g_Winp[i] = make_float2(Win_w[f * 128 + 2 * k2], Win_w[f * 128 + 2 * k2 + 1]);
    } else if (idx < 147456) {
        int i = idx - 114688;
        int k2 = i >> 7, n = i & 127;
        g_Woutp[i] = make_float2(Wout_w[n * 512 + 2 * k2], Wout_w[n * 512 + 2 * k2 + 1]);
    }
}

// hvc = h_V @ W1a^T + b1 (exact fp32); also zero g_dh
__global__ void __launch_bounds__(NT, 1)
hvc_kernel(const float* __restrict__ h_V, const float* __restrict__ W1_w,
           const float* __restrict__ W1_b) {
    extern __shared__ float smh[];
    float* sW  = smh;
    float* sHv = smh + 16384;
    const int tid = threadIdx.x;
    const int nb  = blockIdx.x * 8;
    #pragma unroll
    for (int i = 0; i < 16; ++i) {
        int id4 = i * NT + tid;
        int k4 = id4 >> 7, n = id4 & 127;
        float4 v = ((const float4*)(W1_w + (size_t)n * 512))[k4];
        sW[(4 * k4 + 0) * 128 + n] = v.x;
        sW[(4 * k4 + 1) * 128 + n] = v.y;
        sW[(4 * k4 + 2) * 128 + n] = v.z;
        sW[(4 * k4 + 3) * 128 + n] = v.w;
    }
    {
        int node = tid >> 5, q = tid & 31;
        float4 v = ((const float4*)(h_V + (size_t)(nb + node) * 128))[q];
        *(float4*)(sHv + node * 128 + 4 * q) = v;
        ((float4*)(g_dh + (size_t)nb * 128))[tid] = make_float4(0.f, 0.f, 0.f, 0.f);
    }
    __syncthreads();
    #pragma unroll
    for (int it = 0; it < 4; ++it) {
        int o = it * NT + tid;
        int node = o >> 7, col = o & 127;
        const float* hv = sHv + node * 128;
        float a = W1_b[col];
        #pragma unroll 8
        for (int k = 0; k < 128; ++k) a = fmaf(hv[k], sW[k * 128 + col], a);
        g_hvc[(size_t)(nb + node) * 128 + col] = a;
    }
}

#define CHB 18432
#define CHW (CHB / 4)

// async-stage one 64k B chunk (h,l) from prepped bf16 [n][K]
__device__ __forceinline__ void stage_B_async(unsigned dsth, const __nv_bfloat16* gh,
                                              const __nv_bfloat16* gl, int K,
                                              int c, int tid) {
    #pragma unroll
    for (int i = 0; i < 4; ++i) {
        int idx = i * NT + tid;
        int n = idx >> 3, q = idx & 7;
        unsigned d = dsth + n * 144 + q * 16;
        cpa16(d,       gh + (size_t)n * K + c * 64 + q * 8);
        cpa16(d + CHB, gl + (size_t)n * K + c * 64 + q * 8);
    }
}

// one 64k chunk: acc[64] += A(128x64, bf16) * B^T(split hi/lo): 2 MMAs per step
__device__ __forceinline__ void chunk_mma2(unsigned sA, unsigned sBh, unsigned sBl,
                                           float* acc, unsigned aoff, unsigned boff) {
    #pragma unroll
    for (int v = 0; v < 2; ++v) {
        unsigned ah[2][2][4];
        #pragma unroll
        for (int t = 0; t < 2; ++t)
            #pragma unroll
            for (int sl = 0; sl < 2; ++sl)
                ldsm4(ah[t][sl], sA + aoff + t * 2304 + (2 * v + sl) * 32);
        #pragma unroll
        for (int u = 0; u < 8; ++u) {
            unsigned bh4[4], bl4[4];
            unsigned off = boff + u * 1152 + v * 64;
            ldsm4(bh4, sBh + off);
            ldsm4(bl4, sBl + off);
            #pragma unroll
            for (int t = 0; t < 2; ++t) {
                float* cc = acc + (t * 8 + u) * 4;
                #pragma unroll
                for (int sl = 0; sl < 2; ++sl) {
                    mma16816(cc, ah[t][sl], bh4 + 2 * sl);
                    mma16816(cc, ah[t][sl], bl4 + 2 * sl);
                }
            }
        }
    }
}

// write acc (bias-added, gelu'd) into bf16 chunks (hi only) at smem byte base sm_y
__device__ __forceinline__ void epi_store(char* smem, int sm_y, const float* acc,
                                          const float* badd0, const float* badd1,
                                          int m0, int nb0, int g, int t4) {
    unsigned* y = (unsigned*)(smem + sm_y);
    #pragma unroll
    for (int t = 0; t < 2; ++t) {
        int r1 = m0 + t * 16 + g, r2 = r1 + 8;
        #pragma unroll
        for (int u = 0; u < 8; ++u) {
            int n = nb0 + u * 8 + 2 * t4;
            const float* cc = acc + (t * 8 + u) * 4;
            __nv_bfloat16 ha = __float2bfloat16_rn(gelu_erf(cc[0] + badd0[n]));
            __nv_bfloat16 hb = __float2bfloat16_rn(gelu_erf(cc[1] + badd0[n + 1]));
            __nv_bfloat16 hc = __float2bfloat16_rn(gelu_erf(cc[2] + badd1[n]));
            __nv_bfloat16 hd = __float2bfloat16_rn(gelu_erf(cc[3] + badd1[n + 1]));
            int ch = n >> 6, col = (n & 63) >> 1;
            unsigned* yh = y + ch * CHW;
            yh[r1 * 36 + col] = pack2(ha, hb);
            yh[r2 * 36 + col] = pack2(hc, hd);
        }
    }
}

// ---- edge GEMM smem layout (bytes) ----
#define SM_BIAS 0
#define SM_HVC  1024
#define SM_Y1   3072                    // 2 chunks (hi only); sMsg spans Y1+X
#define SM_X    (SM_Y1 + 2 * CHB)       // A double-buffer (hi only); later Y2 (2 chunks)
#define SM_B    (SM_X + 2 * CHB)        // B double-buffer (2x h/l) = 4 chunks
#define SM_TOT  (SM_B + 4 * CHB)        // 150528

__global__ void __launch_bounds__(NT, 1)
edge_gemm_kernel(const float* __restrict__ h_E, const float* __restrict__ mask_attend,
                 const float* __restrict__ W2_b, const float* __restrict__ W3_b,
                 int n_nodes) {
    extern __shared__ char smem[];
    const int tid = threadIdx.x;
    const int lane = tid & 31;
    const int wid = tid >> 5;
    const int g = lane >> 2, t4 = lane & 3;
    const int wm = wid >> 1, wn = wid & 1;
    const int m0 = wm * 32, nb0 = wn * 64;
    const int base = blockIdx.x * 128;
    const int n0 = base / 48;
    const unsigned sb = (unsigned)__cvta_generic_to_shared(smem);

    const unsigned aoff = (m0 + (lane & 15)) * 144 + (lane >> 4) * 16;
    const unsigned boff = (nb0 + (lane & 7)) * 144 + (lane >> 3) * 16;

    const int ar = tid >> 3, aq = tid & 7;
    const float* heb = h_E + (size_t)base * 384 + aq * 8;

    if (tid < 128) {
        ((float*)(smem + SM_BIAS))[tid]       = W2_b[tid];
        ((float*)(smem + SM_BIAS))[128 + tid] = W3_b[tid];
    }
    for (int t = tid; t < 512; t += NT) {
        int gg = t >> 7, c = t & 127;
        int nd = n0 + gg;
        ((float*)(smem + SM_HVC))[t] = (nd < n_nodes) ? g_hvc[(size_t)nd * 128 + c] : 0.f;
    }

    float acc[64];
    #pragma unroll
    for (int i = 0; i < 64; ++i) acc[i] = 0.f;

    float4 ar0[2], ar1[2], ar2[2], ar3[2];

    #define LOADA(c)                                                          \
      { const float4* p0 = (const float4*)(heb + (size_t)(ar)      * 384 + (c) * 64); \
        const float4* p1 = (const float4*)(heb + (size_t)(ar + 32) * 384 + (c) * 64); \
        const float4* p2 = (const float4*)(heb + (size_t)(ar + 64) * 384 + (c) * 64); \
        const float4* p3 = (const float4*)(heb + (size_t)(ar + 96) * 384 + (c) * 64); \
        ar0[0] = p0[0]; ar0[1] = p0[1]; ar1[0] = p1[0]; ar1[1] = p1[1];       \
        ar2[0] = p2[0]; ar2[1] = p2[1]; ar3[0] = p3[0]; ar3[1] = p3[1]; }

    // convert + store registers into A buffer (hi only)
    #define STOREA(dstb)                                                      \
      { unsigned* dh = (unsigned*)(smem + (dstb));                            \
        float4* rr[4][2] = {{&ar0[0],&ar0[1]},{&ar1[0],&ar1[1]},              \
                            {&ar2[0],&ar2[1]},{&ar3[0],&ar3[1]}};             \
        _Pragma("unroll")                                                     \
        for (int i = 0; i < 4; ++i) {                                         \
            float f[8] = {rr[i][0]->x, rr[i][0]->y, rr[i][0]->z, rr[i][0]->w, \
                          rr[i][1]->x, rr[i][1]->y, rr[i][1]->z, rr[i][1]->w};\
            __nv_bfloat16 hb[8];                                              \
            _Pragma("unroll")                                                 \
            for (int j = 0; j < 8; ++j) hb[j] = __float2bfloat16_rn(f[j]);    \
            int o = (ar + i * 32) * 36 + aq * 4;                              \
            uint4 uh;                                                         \
            uh.x = pack2(hb[0], hb[1]); uh.y = pack2(hb[2], hb[3]);           \
            uh.z = pack2(hb[4], hb[5]); uh.w = pack2(hb[6], hb[7]);           \
            *(uint4*)(dh + o) = uh;                                           \
        } }

    // ---------- GEMM1: h_E @ W1b^T, K=384, double-buffered ----------
    stage_B_async(sb + SM_B, g_W1bh, g_W1bl, 384, 0, tid);
    CP_COMMIT();
    LOADA(0);
    STOREA(SM_X);
    CP_WAIT0();
    __syncthreads();
    for (int c = 0; c < 6; ++c) {
        const int cur = c & 1, nxt = cur ^ 1;
        if (c < 5) {
            stage_B_async(sb + SM_B + nxt * 2 * CHB, g_W1bh, g_W1bl, 384, c + 1, tid);
            CP_COMMIT();
            LOADA(c + 1);
        }
        chunk_mma2(sb + SM_X + cur * CHB,
                   sb + SM_B + cur * 2 * CHB, sb + SM_B + cur * 2 * CHB + CHB,
                   acc, aoff, boff);
        if (c < 5) STOREA(SM_X + nxt * CHB);
        CP_WAIT0();
        __syncthreads();
    }

    // prefetch ALL of W2 into the 4 B buffers
    stage_B_async(sb + SM_B,           g_W2h, g_W2l, 128, 0, tid);
    stage_B_async(sb + SM_B + 2 * CHB, g_W2h, g_W2l, 128, 1, tid);
    CP_COMMIT();

    // epilogue 1: y1 = gelu(D + hvc[node]) -> Y1 chunks (hi only)
    {
        const float* hvc = (const float*)(smem + SM_HVC);
        unsigned* y = (unsigned*)(smem + SM_Y1);
        #pragma unroll
        for (int t = 0; t < 2; ++t) {
            int rr1 = m0 + t * 16 + g, rr2 = rr1 + 8;
            const float* b0 = hvc + ((base + rr1) / 48 - n0) * 128;
            const float* b1 = hvc + ((base + rr2) / 48 - n0) * 128;
            #pragma unroll
            for (int u = 0; u < 8; ++u) {
                int n = nb0 + u * 8 + 2 * t4;
                const float* cc = acc + (t * 8 + u) * 4;
                __nv_bfloat16 ha = __float2bfloat16_rn(gelu_erf(cc[0] + b0[n]));
                __nv_bfloat16 hb2 = __float2bfloat16_rn(gelu_erf(cc[1] + b0[n + 1]));
                __nv_bfloat16 hc = __float2bfloat16_rn(gelu_erf(cc[2] + b1[n]));
                __nv_bfloat16 hd = __float2bfloat16_rn(gelu_erf(cc[3] + b1[n + 1]));
                int ch = n >> 6, col = (n & 63) >> 1;
                unsigned* yh = y + ch * CHW;
                yh[rr1 * 36 + col] = pack2(ha, hb2);
                yh[rr2 * 36 + col] = pack2(hc, hd);
            }
        }
    }
    #pragma unroll
    for (int i = 0; i < 64; ++i) acc[i] = 0.f;
    CP_WAIT0();
    __syncthreads();

    // ---------- GEMM2: Y1 @ W2^T ----------
    chunk_mma2(sb + SM_Y1,       sb + SM_B,           sb + SM_B + CHB,     acc, aoff, boff);
    chunk_mma2(sb + SM_Y1 + CHB, sb + SM_B + 2 * CHB, sb + SM_B + 3 * CHB, acc, aoff, boff);
    __syncthreads();

    // prefetch ALL of W3, overlapped with epilogue 2
    stage_B_async(sb + SM_B,           g_W3h, g_W3l, 128, 0, tid);
    stage_B_async(sb + SM_B + 2 * CHB, g_W3h, g_W3l, 128, 1, tid);
    CP_COMMIT();
    {
        const float* b2 = (const float*)(smem + SM_BIAS);
        epi_store(smem, SM_X, acc, b2, b2, m0, nb0, g, t4);
    }
    #pragma unroll
    for (int i = 0; i < 64; ++i) acc[i] = 0.f;
    CP_WAIT0();
    __syncthreads();

    // ---------- GEMM3: Y2 @ W3^T ----------
    chunk_mma2(sb + SM_X,       sb + SM_B,           sb + SM_B + CHB,     acc, aoff, boff);
    chunk_mma2(sb + SM_X + CHB, sb + SM_B + 2 * CHB, sb + SM_B + 3 * CHB, acc, aoff, boff);
    __syncthreads();

    // epilogue 3: msg*(mask) -> sMsg [n][129] (spans Y1+X); segment sums -> g_dh
    {
        const float* b3 = (const float*)(smem + SM_BIAS) + 128;
        float* sMsg = (float*)(smem + SM_Y1);
        #pragma unroll
        for (int t = 0; t < 2; ++t) {
            int r1 = m0 + t * 16 + g, r2 = r1 + 8;
            float mk1 = mask_attend[base + r1];
            float mk2 = mask_attend[base + r2];
            #pragma unroll
            for (int u = 0; u < 8; ++u) {
                int n = nb0 + u * 8 + 2 * t4;
                const float* cc = acc + (t * 8 + u) * 4;
                sMsg[n * 129 + r1]       = (cc[0] + b3[n])     * mk1;
                sMsg[(n + 1) * 129 + r1] = (cc[1] + b3[n + 1]) * mk1;
                sMsg[n * 129 + r2]       = (cc[2] + b3[n])     * mk2;
                sMsg[(n + 1) * 129 + r2] = (cc[3] + b3[n + 1]) * mk2;
            }
        }
    }
    __syncthreads();
    if (tid < 128) {
        const float* sMsg = (const float*)(smem + SM_Y1);
        int col = tid;
        #pragma unroll
        for (int gg = 0; gg < 4; ++gg) {
            int ng = n0 + gg;
            if (ng >= n_nodes) break;
            int lo = ng * 48 - base, hi = lo + 48;
            if (lo < 0) lo = 0;
            if (hi > 128) hi = 128;
            if (lo < hi) {
                float s = 0.f;
                for (int r = lo; r < hi; ++r) s += sMsg[col * 129 + r];
                atomicAdd(&g_dh[(size_t)ng * 128 + col], s);
            }
        }
    }
}

// node LN1 -> g_Hbuf
__global__ void __launch_bounds__(NT, 1)
node_ln_kernel(const float* __restrict__ h_V,
               const float* __restrict__ ln1_g, const float* __restrict__ ln1_b) {
    const int tid = threadIdx.x;
    const int lid = tid & 31;
    const int node = blockIdx.x * 8 + (tid >> 5);
    float4 dv = ((const float4*)(g_dh + (size_t)node * 128))[lid];
    float4 hv = ((const float4*)(h_V + (size_t)node * 128))[lid];
    float v0 = hv.x + dv.x * (1.0f / 30.0f);
    float v1 = hv.y + dv.y * (1.0f / 30.0f);
    float v2 = hv.z + dv.z * (1.0f / 30.0f);
    float v3 = hv.w + dv.w * (1.0f / 30.0f);
    float s = v0 + v1 + v2 + v3;
    float s2 = v0 * v0 + v1 * v1 + v2 * v2 + v3 * v3;
    #pragma unroll
    for (int off = 16; off > 0; off >>= 1) {
        s  += __shfl_xor_sync(0xffffffffu, s,  off);
        s2 += __shfl_xor_sync(0xffffffffu, s2, off);
    }
    float mean = s * (1.0f / 128.0f);
    float rstd = rsqrtf(s2 * (1.0f / 128.0f) - mean * mean + 1e-5f);
    float4 g = ((const float4*)ln1_g)[lid];
    float4 b = ((const float4*)ln1_b)[lid];
    float4 o;
    o.x = (v0 - mean) * rstd * g.x + b.x;
    o.y = (v1 - mean) * rstd * g.y + b.y;
    o.z = (v2 - mean) * rstd * g.z + b.z;
    o.w = (v3 - mean) * rstd * g.w + b.w;
    ((float4*)(g_Hbuf + (size_t)node * 128))[lid] = o;
}

// ---- FFN (proven fp32 f32x2) ----
#define K2_H   0
#define K2_F   4096
#define K2_O   20480
#define SM2_BYTES  (24576 * 4)
#define INNERG(J, XB, XSTRIDE, WP, WROWF)                              \
  {                                                                    \
    ulonglong2 va = __ldg((const ulonglong2*)(WP));                    \
    ulonglong2 vb = __ldg((const ulonglong2*)((WP) + (WROWF)));        \
    _Pragma("unroll")                                                  \
    for (int j = 0; j < (J); ++j) {                                    \
      u64 xa, xb; lds2(xa, xb, (XB) + j * (XSTRIDE));                  \
      fma2(acc[j][0], xa, va.x); fma2(acc[j][1], xa, va.y);            \
      fma2(acc[j][0], xb, vb.x); fma2(acc[j][1], xb, vb.y);            \
    }                                                                  \
  }

__global__ void __launch_bounds__(NT, 1)
ffn_kernel(const float* __restrict__ mask_V,
           const float* __restrict__ Win_b, const float* __restrict__ Wout_b,
           const float* __restrict__ ln2_g, const float* __restrict__ ln2_b,
           float* __restrict__ out)
{
    extern __shared__ float smf[];
    const int tid = threadIdx.x;
    const int tx  = tid & 31;
    const int ty  = tid >> 5;
    const int wm  = ty >> 1;
    const int wn  = ty & 1;
    const int m0  = wm * 8;
    const int n0  = wn * 64 + 2 * tx;
    const int nb  = blockIdx.x * 32;

    const unsigned sbase = (unsigned)__cvta_generic_to_shared(smf);
    float* sH = smf + K2_H;
    float* sF = smf + K2_F;
    float* sO = smf + K2_O;
    const float* gWin  = (const float*)g_Winp;
    const float* gWout = (const float*)g_Woutp + 2 * n0;

    {
        const float4* src = (const float4*)(g_Hbuf + (size_t)nb * Hdim);
        float4* dst = (float4*)sH;
        #pragma unroll
        for (int i = 0; i < 4; ++i) dst[i * NT + tid] = src[i * NT + tid];
    }
    __syncthreads();

    u64 acc[8][2];
    for (int nblk = 0; nblk < 4; ++nblk) {
        #pragma unroll
        for (int j = 0; j < 8; ++j) { acc[j][0] = 0ULL; acc[j][1] = 0ULL; }
        {
            const unsigned xrow = sbase + K2_H * 4 + m0 * 512;
            const float* wp = gWin + nblk * 256 + 2 * n0;
            #pragma unroll 4
            for (int it = 0; it < 32; ++it)
                INNERG(8, xrow + it * 16, 512, wp + it * 2048, 1024);
        }
        float2 bv = *(const float2*)(Win_b + nblk * 128 + n0);
        #pragma unroll
        for (int j = 0; j < 8; ++j) {
            float2 r;
            r.x = gelu_erf(hadd(acc[j][0]) + bv.x);
            r.y = gelu_erf(hadd(acc[j][1]) + bv.y);
            *(float2*)(sF + (m0 + j) * 512 + nblk * 128 + n0) = r;
        }
    }
    __syncthreads();

    #pragma unroll
    for (int j = 0; j < 8; ++j) { acc[j][0] = 0ULL; acc[j][1] = 0ULL; }
    for (int kt = 0; kt < 4; ++kt) {
        const unsigned xrow = sbase + K2_F * 4 + m0 * 2048;
        const float* wp = gWout + kt * 16384;
        #pragma unroll 4
        for (int it = 0; it < 32; ++it)
            INNERG(8, xrow + kt * 512 + it * 16, 2048, wp + it * 512, 256);
    }
    {
        float2 bv = *(const float2*)(Wout_b + n0);
        #pragma unroll
        for (int j = 0; j < 8; ++j) {
            float2 r;
            r.x = hadd(acc[j][0]) + bv.x;
            r.y = hadd(acc[j][1]) + bv.y;
            *(float2*)(sO + (m0 + j) * 128 + n0) = r;
        }
    }
    __syncthreads();

    #pragma unroll
    for (int rr = 0; rr < 4; ++rr) {
        int r = ty + rr * 8;
        float v[4];
        float s = 0.f, s2 = 0.f;
        #pragma unroll
        for (int i = 0; i < 4; ++i) {
            int n = tx + i * 32;
            v[i] = sH[r * 128 + n] + sO[r * 128 + n];
            s += v[i]; s2 += v[i] * v[i];
        }
        #pragma unroll
        for (int off = 16; off > 0; off >>= 1) {
            s  += __shfl_xor_sync(0xffffffffu, s,  off);
            s2 += __shfl_xor_sync(0xffffffffu, s2, off);
        }
        float mean = s * (1.0f / 128.0f);
        float rstd = rsqrtf(s2 * (1.0f / 128.0f) - mean * mean + 1e-5f);
        float mv = mask_V[nb + r];
        #pragma unroll
        for (int i = 0; i < 4; ++i) {
            int n = tx + i * 32;
            out[(size_t)(nb + r) * Hdim + n] =
                mv * ((v[i] - mean) * rstd * ln2_g[n] + ln2_b[n]);
        }
    }
}

extern "C" void kernel_launch(void* const* d_in, const int* in_sizes, int n_in,
                              void* d_out, int out_size) {
    const float* h_V         = (const float*)d_in[0];
    const float* h_E         = (const float*)d_in[1];
    const float* mask_V      = (const float*)d_in[2];
    const float* mask_attend = (const float*)d_in[3];
    const float* W1_w        = (const float*)d_in[4];
    const float* W1_b        = (const float*)d_in[5];
    const float* W2_w        = (const float*)d_in[6];
    const float* W2_b        = (const float*)d_in[7];
    const float* W3_w        = (const float*)d_in[8];
    const float* W3_b        = (const float*)d_in[9];
    const float* ln1_g       = (const float*)d_in[10];
    const float* ln1_b       = (const float*)d_in[11];
    const float* ln2_g       = (const float*)d_in[12];
    const float* ln2_b       = (const float*)d_in[13];
    const float* Win_w       = (const float*)d_in[14];
    const float* Win_b       = (const float*)d_in[15];
    const float* Wout_w      = (const float*)d_in[16];
    const float* Wout_b      = (const float*)d_in[17];

    int nodes = in_sizes[0] / Hdim;        // 4096
    int tiles = (nodes * KNB + 127) / 128; // 1536

    prep_weights<<<576, 256>>>(W1_w, W2_w, W3_w, Win_w, Wout_w);

    cudaFuncSetAttribute(hvc_kernel, cudaFuncAttributeMaxDynamicSharedMemorySize, 73728);
    hvc_kernel<<<nodes / 8, NT, 73728>>>(h_V, W1_w, W1_b);

    cudaFuncSetAttribute(edge_gemm_kernel, cudaFuncAttributeMaxDynamicSharedMemorySize, SM_TOT);
    edge_gemm_kernel<<<tiles, NT, SM_TOT>>>(h_E, mask_attend, W2_b, W3_b, nodes);

    node_ln_kernel<<<nodes / 8, NT>>>(h_V, ln1_g, ln1_b);

    cudaFuncSetAttribute(ffn_kernel, cudaFuncAttributeMaxDynamicSharedMemorySize, SM2_BYTES);
    ffn_kernel<<<nodes / 32, NT, SM2_BYTES>>>(mask_V, Win_b, Wout_b, ln2_g, ln2_b, (float*)d_out);
}

// round 16
// speedup vs baseline: 1.7963x; 1.2248x over previous
#include <cuda_runtime.h>
#include <cuda_bf16.h>
#include <math.h>

#define Hdim 128
#define KNB  48
#define NT   256
typedef unsigned long long u64;

__device__ __nv_bfloat16 g_W1bh[128 * 384];   // [n][k]
__device__ __nv_bfloat16 g_W2h[128 * 128];
__device__ __nv_bfloat16 g_W3h[128 * 128];
__device__ float2 g_Winp[64 * 512];
__device__ float2 g_Woutp[256 * 128];
__device__ float  g_hvc[4096 * 128];
__device__ float  g_dh[4096 * 128];
__device__ float  g_Hbuf[4096 * 128];

__device__ __forceinline__ float gelu_erf(float x) {
    return 0.5f * x * (1.0f + erff(x * 0.70710678118654752440f));
}
__device__ __forceinline__ void fma2(u64& d, u64 a, u64 b) {
    asm("fma.rn.f32x2 %0, %1, %2, %0;" : "+l"(d) : "l"(a), "l"(b));
}
__device__ __forceinline__ void lds2(u64& a, u64& b, unsigned addr) {
    asm volatile("ld.shared.v2.b64 {%0,%1}, [%2];" : "=l"(a), "=l"(b) : "r"(addr));
}
__device__ __forceinline__ float hadd(u64 p) {
    float lo, hi;
    asm("mov.b64 {%0,%1}, %2;" : "=f"(lo), "=f"(hi) : "l"(p));
    return lo + hi;
}
__device__ __forceinline__ unsigned pack2(__nv_bfloat16 a, __nv_bfloat16 b) {
    return ((unsigned)__bfloat16_as_ushort(b) << 16) | (unsigned)__bfloat16_as_ushort(a);
}
__device__ __forceinline__ void mma16816(float* c, const unsigned* a, const unsigned* b) {
    asm volatile(
        "mma.sync.aligned.m16n8k16.row.col.f32.bf16.bf16.f32 "
        "{%0,%1,%2,%3}, {%4,%5,%6,%7}, {%8,%9}, {%0,%1,%2,%3};"
        : "+f"(c[0]), "+f"(c[1]), "+f"(c[2]), "+f"(c[3])
        : "r"(a[0]), "r"(a[1]), "r"(a[2]), "r"(a[3]), "r"(b[0]), "r"(b[1]));
}
__device__ __forceinline__ void ldsm4(unsigned* r, unsigned addr) {
    asm volatile("ldmatrix.sync.aligned.m8n8.x4.shared.b16 {%0,%1,%2,%3}, [%4];"
        : "=r"(r[0]), "=r"(r[1]), "=r"(r[2]), "=r"(r[3]) : "r"(addr));
}
__device__ __forceinline__ void cpa16(unsigned dst, const void* src) {
    asm volatile("cp.async.ca.shared.global [%0], [%1], 16;" :: "r"(dst), "l"(src));
}
#define CP_COMMIT() asm volatile("cp.async.commit_group;" ::: "memory")
#define CP_WAIT0()  asm volatile("cp.async.wait_group 0;" ::: "memory")

__global__ void prep_weights(const float* __restrict__ W1_w, const float* __restrict__ W2_w,
                             const float* __restrict__ W3_w, const float* __restrict__ Win_w,
                             const float* __restrict__ Wout_w) {
    int idx = blockIdx.x * blockDim.x + threadIdx.x;
    if (idx < 49152) {
        int n = idx / 384, k = idx % 384;
        g_W1bh[idx] = __float2bfloat16_rn(W1_w[n * 512 + 128 + k]);
    } else if (idx < 65536) {
        int i = idx - 49152;
        g_W2h[i] = __float2bfloat16_rn(W2_w[i]);
    } else if (idx < 81920) {
        int i = idx - 65536;
        g_W3h[i] = __float2bfloat16_rn(W3_w[i]);
    } else if (idx < 114688) {
        int i = idx - 81920;
        int k2 = i >> 9, f = i & 511;
        g_Winp[i] = make_float2(Win_w[f * 128 + 2 * k2], Win_w[f * 128 + 2 * k2 + 1]);
    } else if (idx < 147456) {
        int i = idx - 114688;
        int k2 = i >> 7, n = i & 127;
        g_Woutp[i] = make_float2(Wout_w[n * 512 + 2 * k2], Wout_w[n * 512 + 2 * k2 + 1]);
    }
}

// hvc = h_V @ W1a^T + b1 (exact fp32); also zero g_dh
__global__ void __launch_bounds__(NT, 1)
hvc_kernel(const float* __restrict__ h_V, const float* __restrict__ W1_w,
           const float* __restrict__ W1_b) {
    extern __shared__ float smh[];
    float* sW  = smh;
    float* sHv = smh + 16384;
    const int tid = threadIdx.x;
    const int nb  = blockIdx.x * 8;
    #pragma unroll
    for (int i = 0; i < 16; ++i) {
        int id4 = i * NT + tid;
        int k4 = id4 >> 7, n = id4 & 127;
        float4 v = ((const float4*)(W1_w + (size_t)n * 512))[k4];
        sW[(4 * k4 + 0) * 128 + n] = v.x;
        sW[(4 * k4 + 1) * 128 + n] = v.y;
        sW[(4 * k4 + 2) * 128 + n] = v.z;
        sW[(4 * k4 + 3) * 128 + n] = v.w;
    }
    {
        int node = tid >> 5, q = tid & 31;
        float4 v = ((const float4*)(h_V + (size_t)(nb + node) * 128))[q];
        *(float4*)(sHv + node * 128 + 4 * q) = v;
        ((float4*)(g_dh + (size_t)nb * 128))[tid] = make_float4(0.f, 0.f, 0.f, 0.f);
    }
    __syncthreads();
    #pragma unroll
    for (int it = 0; it < 4; ++it) {
        int o = it * NT + tid;
        int node = o >> 7, col = o & 127;
        const float* hv = sHv + node * 128;
        float a = W1_b[col];
        #pragma unroll 8
        for (int k = 0; k < 128; ++k) a = fmaf(hv[k], sW[k * 128 + col], a);
        g_hvc[(size_t)(nb + node) * 128 + col] = a;
    }
}

#define CHB 18432
#define CHW (CHB / 4)

// async-stage one 64k B chunk (bf16) from prepped [n][K]
__device__ __forceinline__ void stage_B_async(unsigned dst, const __nv_bfloat16* gw,
                                              int K, int c, int tid) {
    #pragma unroll
    for (int i = 0; i < 4; ++i) {
        int idx = i * NT + tid;
        int n = idx >> 3, q = idx & 7;
        cpa16(dst + n * 144 + q * 16, gw + (size_t)n * K + c * 64 + q * 8);
    }
}

// one 64k chunk: acc[64] += A(128x64, bf16) * B^T(bf16): 1 MMA per step
__device__ __forceinline__ void chunk_mma1(unsigned sA, unsigned sB,
                                           float* acc, unsigned aoff, unsigned boff) {
    #pragma unroll
    for (int v = 0; v < 2; ++v) {
        unsigned ah[2][2][4];
        #pragma unroll
        for (int t = 0; t < 2; ++t)
            #pragma unroll
            for (int sl = 0; sl < 2; ++sl)
                ldsm4(ah[t][sl], sA + aoff + t * 2304 + (2 * v + sl) * 32);
        #pragma unroll
        for (int u = 0; u < 8; ++u) {
            unsigned bh4[4];
            ldsm4(bh4, sB + boff + u * 1152 + v * 64);
            #pragma unroll
            for (int t = 0; t < 2; ++t) {
                float* cc = acc + (t * 8 + u) * 4;
                mma16816(cc, ah[t][0], bh4);
                mma16816(cc, ah[t][1], bh4 + 2);
            }
        }
    }
}

// write acc (bias-added, gelu'd) into bf16 chunks at smem byte base sm_y
__device__ __forceinline__ void epi_store(char* smem, int sm_y, const float* acc,
                                          const float* badd0, const float* badd1,
                                          int m0, int nb0, int g, int t4) {
    unsigned* y = (unsigned*)(smem + sm_y);
    #pragma unroll
    for (int t = 0; t < 2; ++t) {
        int r1 = m0 + t * 16 + g, r2 = r1 + 8;
        #pragma unroll
        for (int u = 0; u < 8; ++u) {
            int n = nb0 + u * 8 + 2 * t4;
            const float* cc = acc + (t * 8 + u) * 4;
            __nv_bfloat16 ha = __float2bfloat16_rn(gelu_erf(cc[0] + badd0[n]));
            __nv_bfloat16 hb = __float2bfloat16_rn(gelu_erf(cc[1] + badd0[n + 1]));
            __nv_bfloat16 hc = __float2bfloat16_rn(gelu_erf(cc[2] + badd1[n]));
            __nv_bfloat16 hd = __float2bfloat16_rn(gelu_erf(cc[3] + badd1[n + 1]));
            int ch = n >> 6, col = (n & 63) >> 1;
            unsigned* yh = y + ch * CHW;
            yh[r1 * 36 + col] = pack2(ha, hb);
            yh[r2 * 36 + col] = pack2(hc, hd);
        }
    }
}

// ---- edge GEMM smem layout (bytes) ----
#define SM_BIAS 0
#define SM_HVC  1024
#define SM_Y1   3072                    // 2 chunks; sMsg spans Y1+X
#define SM_X    (SM_Y1 + 2 * CHB)       // A double-buffer; later Y2 (2 chunks)
#define SM_B    (SM_X + 2 * CHB)        // B double-buffer (2 chunks)
#define SM_TOT  (SM_B + 2 * CHB)        // 113664

__global__ void __launch_bounds__(NT, 1)
edge_gemm_kernel(const float* __restrict__ h_E, const float* __restrict__ mask_attend,
                 const float* __restrict__ W2_b, const float* __restrict__ W3_b,
                 int n_nodes) {
    extern __shared__ char smem[];
    const int tid = threadIdx.x;
    const int lane = tid & 31;
    const int wid = tid >> 5;
    const int g = lane >> 2, t4 = lane & 3;
    const int wm = wid >> 1, wn = wid & 1;
    const int m0 = wm * 32, nb0 = wn * 64;
    const int base = blockIdx.x * 128;
    const int n0 = base / 48;
    const unsigned sb = (unsigned)__cvta_generic_to_shared(smem);

    const unsigned aoff = (m0 + (lane & 15)) * 144 + (lane >> 4) * 16;
    const unsigned boff = (nb0 + (lane & 7)) * 144 + (lane >> 3) * 16;

    const int ar = tid >> 3, aq = tid & 7;
    const float* heb = h_E + (size_t)base * 384 + aq * 8;

    if (tid < 128) {
        ((float*)(smem + SM_BIAS))[tid]       = W2_b[tid];
        ((float*)(smem + SM_BIAS))[128 + tid] = W3_b[tid];
    }
    for (int t = tid; t < 512; t += NT) {
        int gg = t >> 7, c = t & 127;
        int nd = n0 + gg;
        ((float*)(smem + SM_HVC))[t] = (nd < n_nodes) ? g_hvc[(size_t)nd * 128 + c] : 0.f;
    }

    float acc[64];
    #pragma unroll
    for (int i = 0; i < 64; ++i) acc[i] = 0.f;

    float4 ar0[2], ar1[2], ar2[2], ar3[2];

    #define LOADA(c)                                                          \
      { const float4* p0 = (const float4*)(heb + (size_t)(ar)      * 384 + (c) * 64); \
        const float4* p1 = (const float4*)(heb + (size_t)(ar + 32) * 384 + (c) * 64); \
        const float4* p2 = (const float4*)(heb + (size_t)(ar + 64) * 384 + (c) * 64); \
        const float4* p3 = (const float4*)(heb + (size_t)(ar + 96) * 384 + (c) * 64); \
        ar0[0] = p0[0]; ar0[1] = p0[1]; ar1[0] = p1[0]; ar1[1] = p1[1];       \
        ar2[0] = p2[0]; ar2[1] = p2[1]; ar3[0] = p3[0]; ar3[1] = p3[1]; }

    #define STOREA(dstb)                                                      \
      { unsigned* dh = (unsigned*)(smem + (dstb));                            \
        float4* rr[4][2] = {{&ar0[0],&ar0[1]},{&ar1[0],&ar1[1]},              \
                            {&ar2[0],&ar2[1]},{&ar3[0],&ar3[1]}};             \
        _Pragma("unroll")                                                     \
        for (int i = 0; i < 4; ++i) {                                         \
            float f[8] = {rr[i][0]->x, rr[i][0]->y, rr[i][0]->z, rr[i][0]->w, \
                          rr[i][1]->x, rr[i][1]->y, rr[i][1]->z, rr[i][1]->w};\
            __nv_bfloat16 hb[8];                                              \
            _Pragma("unroll")                                                 \
            for (int j = 0; j < 8; ++j) hb[j] = __float2bfloat16_rn(f[j]);    \
            int o = (ar + i * 32) * 36 + aq * 4;                              \
            uint4 uh;                                                         \
            uh.x = pack2(hb[0], hb[1]); uh.y = pack2(hb[2], hb[3]);           \
            uh.z = pack2(hb[4], hb[5]); uh.w = pack2(hb[6], hb[7]);           \
            *(uint4*)(dh + o) = uh;                                           \
        } }

    // ---------- GEMM1: h_E @ W1b^T, K=384, double-buffered ----------
    stage_B_async(sb + SM_B, g_W1bh, 384, 0, tid);
    CP_COMMIT();
    LOADA(0);
    STOREA(SM_X);
    CP_WAIT0();
    __syncthreads();
    for (int c = 0; c < 6; ++c) {
        const int cur = c & 1, nxt = cur ^ 1;
        if (c < 5) {
            stage_B_async(sb + SM_B + nxt * CHB, g_W1bh, 384, c + 1, tid);
            CP_COMMIT();
            LOADA(c + 1);
        }
        chunk_mma1(sb + SM_X + cur * CHB, sb + SM_B + cur * CHB, acc, aoff, boff);
        if (c < 5) STOREA(SM_X + nxt * CHB);
        CP_WAIT0();
        __syncthreads();
    }

    // prefetch ALL of W2 into both B buffers
    stage_B_async(sb + SM_B,       g_W2h, 128, 0, tid);
    stage_B_async(sb + SM_B + CHB, g_W2h, 128, 1, tid);
    CP_COMMIT();

    // epilogue 1: y1 = gelu(D + hvc[node]) -> Y1 chunks
    {
        const float* hvc = (const float*)(smem + SM_HVC);
        unsigned* y = (unsigned*)(smem + SM_Y1);
        #pragma unroll
        for (int t = 0; t < 2; ++t) {
            int rr1 = m0 + t * 16 + g, rr2 = rr1 + 8;
            const float* b0 = hvc + ((base + rr1) / 48 - n0) * 128;
            const float* b1 = hvc + ((base + rr2) / 48 - n0) * 128;
            #pragma unroll
            for (int u = 0; u < 8; ++u) {
                int n = nb0 + u * 8 + 2 * t4;
                const float* cc = acc + (t * 8 + u) * 4;
                __nv_bfloat16 ha  = __float2bfloat16_rn(gelu_erf(cc[0] + b0[n]));
                __nv_bfloat16 hb2 = __float2bfloat16_rn(gelu_erf(cc[1] + b0[n + 1]));
                __nv_bfloat16 hc  = __float2bfloat16_rn(gelu_erf(cc[2] + b1[n]));
                __nv_bfloat16 hd  = __float2bfloat16_rn(gelu_erf(cc[3] + b1[n + 1]));
                int ch = n >> 6, col = (n & 63) >> 1;
                unsigned* yh = y + ch * CHW;
                yh[rr1 * 36 + col] = pack2(ha, hb2);
                yh[rr2 * 36 + col] = pack2(hc, hd);
            }
        }
    }
    #pragma unroll
    for (int i = 0; i < 64; ++i) acc[i] = 0.f;
    CP_WAIT0();
    __syncthreads();

    // ---------- GEMM2: Y1 @ W2^T ----------
    chunk_mma1(sb + SM_Y1,       sb + SM_B,       acc, aoff, boff);
    chunk_mma1(sb + SM_Y1 + CHB, sb + SM_B + CHB, acc, aoff, boff);
    __syncthreads();

    // prefetch ALL of W3, overlapped with epilogue 2
    stage_B_async(sb + SM_B,       g_W3h, 128, 0, tid);
    stage_B_async(sb + SM_B + CHB, g_W3h, 128, 1, tid);
    CP_COMMIT();
    {
        const float* b2 = (const float*)(smem + SM_BIAS);
        epi_store(smem, SM_X, acc, b2, b2, m0, nb0, g, t4);
    }
    #pragma unroll
    for (int i = 0; i < 64; ++i) acc[i] = 0.f;
    CP_WAIT0();
    __syncthreads();

    // ---------- GEMM3: Y2 @ W3^T ----------
    chunk_mma1(sb + SM_X,       sb + SM_B,       acc, aoff, boff);
    chunk_mma1(sb + SM_X + CHB, sb + SM_B + CHB, acc, aoff, boff);
    __syncthreads();

    // epilogue 3: msg*(mask) -> sMsg [n][129] (spans Y1+X); segment sums -> g_dh
    {
        const float* b3 = (const float*)(smem + SM_BIAS) + 128;
        float* sMsg = (float*)(smem + SM_Y1);
        #pragma unroll
        for (int t = 0; t < 2; ++t) {
            int r1 = m0 + t * 16 + g, r2 = r1 + 8;
            float mk1 = mask_attend[base + r1];
            float mk2 = mask_attend[base + r2];
            #pragma unroll
            for (int u = 0; u < 8; ++u) {
                int n = nb0 + u * 8 + 2 * t4;
                const float* cc = acc + (t * 8 + u) * 4;
                sMsg[n * 129 + r1]       = (cc[0] + b3[n])     * mk1;
                sMsg[(n + 1) * 129 + r1] = (cc[1] + b3[n + 1]) * mk1;
                sMsg[n * 129 + r2]       = (cc[2] + b3[n])     * mk2;
                sMsg[(n + 1) * 129 + r2] = (cc[3] + b3[n + 1]) * mk2;
            }
        }
    }
    __syncthreads();
    if (tid < 128) {
        const float* sMsg = (const float*)(smem + SM_Y1);
        int col = tid;
        #pragma unroll
        for (int gg = 0; gg < 4; ++gg) {
            int ng = n0 + gg;
            if (ng >= n_nodes) break;
            int lo = ng * 48 - base, hi = lo + 48;
            if (lo < 0) lo = 0;
            if (hi > 128) hi = 128;
            if (lo < hi) {
                float s = 0.f;
                for (int r = lo; r < hi; ++r) s += sMsg[col * 129 + r];
                atomicAdd(&g_dh[(size_t)ng * 128 + col], s);
            }
        }
    }
}

// node LN1 -> g_Hbuf
__global__ void __launch_bounds__(NT, 1)
node_ln_kernel(const float* __restrict__ h_V,
               const float* __restrict__ ln1_g, const float* __restrict__ ln1_b) {
    const int tid = threadIdx.x;
    const int lid = tid & 31;
    const int node = blockIdx.x * 8 + (tid >> 5);
    float4 dv = ((const float4*)(g_dh + (size_t)node * 128))[lid];
    float4 hv = ((const float4*)(h_V + (size_t)node * 128))[lid];
    float v0 = hv.x + dv.x * (1.0f / 30.0f);
    float v1 = hv.y + dv.y * (1.0f / 30.0f);
    float v2 = hv.z + dv.z * (1.0f / 30.0f);
    float v3 = hv.w + dv.w * (1.0f / 30.0f);
    float s = v0 + v1 + v2 + v3;
    float s2 = v0 * v0 + v1 * v1 + v2 * v2 + v3 * v3;
    #pragma unroll
    for (int off = 16; off > 0; off >>= 1) {
        s  += __shfl_xor_sync(0xffffffffu, s,  off);
        s2 += __shfl_xor_sync(0xffffffffu, s2, off);
    }
    float mean = s * (1.0f / 128.0f);
    float rstd = rsqrtf(s2 * (1.0f / 128.0f) - mean * mean + 1e-5f);
    float4 g = ((const float4*)ln1_g)[lid];
    float4 b = ((const float4*)ln1_b)[lid];
    float4 o;
    o.x = (v0 - mean) * rstd * g.x + b.x;
    o.y = (v1 - mean) * rstd * g.y + b.y;
    o.z = (v2 - mean) * rstd * g.z + b.z;
    o.w = (v3 - mean) * rstd * g.w + b.w;
    ((float4*)(g_Hbuf + (size_t)node * 128))[lid] = o;
}

// ---- FFN (proven fp32 f32x2) ----
#define K2_H   0
#define K2_F   4096
#define K2_O   20480
#define SM2_BYTES  (24576 * 4)
#define INNERG(J, XB, XSTRIDE, WP, WROWF)                              \
  {                                                                    \
    ulonglong2 va = __ldg((const ulonglong2*)(WP));                    \
    ulonglong2 vb = __ldg((const ulonglong2*)((WP) + (WROWF)));        \
    _Pragma("unroll")                                                  \
    for (int j = 0; j < (J); ++j) {                                    \
      u64 xa, xb; lds2(xa, xb, (XB) + j * (XSTRIDE));                  \
      fma2(acc[j][0], xa, va.x); fma2(acc[j][1], xa, va.y);            \
      fma2(acc[j][0], xb, vb.x); fma2(acc[j][1], xb, vb.y);            \
    }                                                                  \
  }

__global__ void __launch_bounds__(NT, 1)
ffn_kernel(const float* __restrict__ mask_V,
           const float* __restrict__ Win_b, const float* __restrict__ Wout_b,
           const float* __restrict__ ln2_g, const float* __restrict__ ln2_b,
           float* __restrict__ out)
{
    extern __shared__ float smf[];
    const int tid = threadIdx.x;
    const int tx  = tid & 31;
    const int ty  = tid >> 5;
    const int wm  = ty >> 1;
    const int wn  = ty & 1;
    const int m0  = wm * 8;
    const int n0  = wn * 64 + 2 * tx;
    const int nb  = blockIdx.x * 32;

    const unsigned sbase = (unsigned)__cvta_generic_to_shared(smf);
    float* sH = smf + K2_H;
    float* sF = smf + K2_F;
    float* sO = smf + K2_O;
    const float* gWin  = (const float*)g_Winp;
    const float* gWout = (const float*)g_Woutp + 2 * n0;

    {
        const float4* src = (const float4*)(g_Hbuf + (size_t)nb * Hdim);
        float4* dst = (float4*)sH;
        #pragma unroll
        for (int i = 0; i < 4; ++i) dst[i * NT + tid] = src[i * NT + tid];
    }
    __syncthreads();

    u64 acc[8][2];
    for (int nblk = 0; nblk < 4; ++nblk) {
        #pragma unroll
        for (int j = 0; j < 8; ++j) { acc[j][0] = 0ULL; acc[j][1] = 0ULL; }
        {
            const unsigned xrow = sbase + K2_H * 4 + m0 * 512;
            const float* wp = gWin + nblk * 256 + 2 * n0;
            #pragma unroll 4
            for (int it = 0; it < 32; ++it)
                INNERG(8, xrow + it * 16, 512, wp + it * 2048, 1024);
        }
        float2 bv = *(const float2*)(Win_b + nblk * 128 + n0);
        #pragma unroll
        for (int j = 0; j < 8; ++j) {
            float2 r;
            r.x = gelu_erf(hadd(acc[j][0]) + bv.x);
            r.y = gelu_erf(hadd(acc[j][1]) + bv.y);
            *(float2*)(sF + (m0 + j) * 512 + nblk * 128 + n0) = r;
        }
    }
    __syncthreads();

    #pragma unroll
    for (int j = 0; j < 8; ++j) { acc[j][0] = 0ULL; acc[j][1] = 0ULL; }
    for (int kt = 0; kt < 4; ++kt) {
        const unsigned xrow = sbase + K2_F * 4 + m0 * 2048;
        const float* wp = gWout + kt * 16384;
        #pragma unroll 4
        for (int it = 0; it < 32; ++it)
            INNERG(8, xrow + kt * 512 + it * 16, 2048, wp + it * 512, 256);
    }
    {
        float2 bv = *(const float2*)(Wout_b + n0);
        #pragma unroll
        for (int j = 0; j < 8; ++j) {
            float2 r;
            r.x = hadd(acc[j][0]) + bv.x;
            r.y = hadd(acc[j][1]) + bv.y;
            *(float2*)(sO + (m0 + j) * 128 + n0) = r;
        }
    }
    __syncthreads();

    #pragma unroll
    for (int rr = 0; rr < 4; ++rr) {
        int r = ty + rr * 8;
        float v[4];
        float s = 0.f, s2 = 0.f;
        #pragma unroll
        for (int i = 0; i < 4; ++i) {
            int n = tx + i * 32;
            v[i] = sH[r * 128 + n] + sO[r * 128 + n];
            s += v[i]; s2 += v[i] * v[i];
        }
        #pragma unroll
        for (int off = 16; off > 0; off >>= 1) {
            s  += __shfl_xor_sync(0xffffffffu, s,  off);
            s2 += __shfl_xor_sync(0xffffffffu, s2, off);
        }
        float mean = s * (1.0f / 128.0f);
        float rstd = rsqrtf(s2 * (1.0f / 128.0f) - mean * mean + 1e-5f);
        float mv = mask_V[nb + r];
        #pragma unroll
        for (int i = 0; i < 4; ++i) {
            int n = tx + i * 32;
            out[(size_t)(nb + r) * Hdim + n] =
                mv * ((v[i] - mean) * rstd * ln2_g[n] + ln2_b[n]);
        }
    }
}

extern "C" void kernel_launch(void* const* d_in, const int* in_sizes, int n_in,
                              void* d_out, int out_size) {
    const float* h_V         = (const float*)d_in[0];
    const float* h_E         = (const float*)d_in[1];
    const float* mask_V      = (const float*)d_in[2];
    const float* mask_attend = (const float*)d_in[3];
    const float* W1_w        = (const float*)d_in[4];
    const float* W1_b        = (const float*)d_in[5];
    const float* W2_w        = (const float*)d_in[6];
    const float* W2_b        = (const float*)d_in[7];
    const float* W3_w        = (const float*)d_in[8];
    const float* W3_b        = (const float*)d_in[9];
    const float* ln1_g       = (const float*)d_in[10];
    const float* ln1_b       = (const float*)d_in[11];
    const float* ln2_g       = (const float*)d_in[12];
    const float* ln2_b       = (const float*)d_in[13];
    const float* Win_w       = (const float*)d_in[14];
    const float* Win_b       = (const float*)d_in[15];
    const float* Wout_w      = (const float*)d_in[16];
    const float* Wout_b      = (const float*)d_in[17];

    int nodes = in_sizes[0] / Hdim;        // 4096
    int tiles = (nodes * KNB + 127) / 128; // 1536

    prep_weights<<<576, 256>>>(W1_w, W2_w, W3_w, Win_w, Wout_w);

    cudaFuncSetAttribute(hvc_kernel, cudaFuncAttributeMaxDynamicSharedMemorySize, 73728);
    hvc_kernel<<<nodes / 8, NT, 73728>>>(h_V, W1_w, W1_b);

    cudaFuncSetAttribute(edge_gemm_kernel, cudaFuncAttributeMaxDynamicSharedMemorySize, SM_TOT);
    edge_gemm_kernel<<<tiles, NT, SM_TOT>>>(h_E, mask_attend, W2_b, W3_b, nodes);

    node_ln_kernel<<<nodes / 8, NT>>>(h_V, ln1_g, ln1_b);

    cudaFuncSetAttribute(ffn_kernel, cudaFuncAttributeMaxDynamicSharedMemorySize, SM2_BYTES);
    ffn_kernel<<<nodes / 32, NT, SM2_BYTES>>>(mask_V, Win_b, Wout_b, ln2_g, ln2_b, (float*)d_out);
}

// round 17
// speedup vs baseline: 1.8004x; 1.0023x over previous
#include <cuda_runtime.h>
#include <cuda_bf16.h>
#include <math.h>

#define Hdim 128
#define KNB  48
#define NT   256
typedef unsigned long long u64;

__device__ __nv_bfloat16 g_W1bh[128 * 384];   // [n][k]
__device__ __nv_bfloat16 g_W2h[128 * 128];
__device__ __nv_bfloat16 g_W3h[128 * 128];
__device__ float2 g_Winp[64 * 512];
__device__ float2 g_Woutp[256 * 128];
__device__ float  g_hvc[4096 * 128];
__device__ float  g_dh[4096 * 128];

__device__ __forceinline__ float gelu_erf(float x) {
    return 0.5f * x * (1.0f + erff(x * 0.70710678118654752440f));
}
__device__ __forceinline__ void fma2(u64& d, u64 a, u64 b) {
    asm("fma.rn.f32x2 %0, %1, %2, %0;" : "+l"(d) : "l"(a), "l"(b));
}
__device__ __forceinline__ void lds2(u64& a, u64& b, unsigned addr) {
    asm volatile("ld.shared.v2.b64 {%0,%1}, [%2];" : "=l"(a), "=l"(b) : "r"(addr));
}
__device__ __forceinline__ float hadd(u64 p) {
    float lo, hi;
    asm("mov.b64 {%0,%1}, %2;" : "=f"(lo), "=f"(hi) : "l"(p));
    return lo + hi;
}
__device__ __forceinline__ unsigned pack2(__nv_bfloat16 a, __nv_bfloat16 b) {
    return ((unsigned)__bfloat16_as_ushort(b) << 16) | (unsigned)__bfloat16_as_ushort(a);
}
__device__ __forceinline__ void mma16816(float* c, const unsigned* a, const unsigned* b) {
    asm volatile(
        "mma.sync.aligned.m16n8k16.row.col.f32.bf16.bf16.f32 "
        "{%0,%1,%2,%3}, {%4,%5,%6,%7}, {%8,%9}, {%0,%1,%2,%3};"
        : "+f"(c[0]), "+f"(c[1]), "+f"(c[2]), "+f"(c[3])
        : "r"(a[0]), "r"(a[1]), "r"(a[2]), "r"(a[3]), "r"(b[0]), "r"(b[1]));
}
__device__ __forceinline__ void ldsm4(unsigned* r, unsigned addr) {
    asm volatile("ldmatrix.sync.aligned.m8n8.x4.shared.b16 {%0,%1,%2,%3}, [%4];"
        : "=r"(r[0]), "=r"(r[1]), "=r"(r[2]), "=r"(r[3]) : "r"(addr));
}
__device__ __forceinline__ void cpa16(unsigned dst, const void* src) {
    asm volatile("cp.async.ca.shared.global [%0], [%1], 16;" :: "r"(dst), "l"(src));
}
#define CP_COMMIT() asm volatile("cp.async.commit_group;" ::: "memory")
#define CP_WAIT0()  asm volatile("cp.async.wait_group 0;" ::: "memory")

__global__ void prep_weights(const float* __restrict__ W1_w, const float* __restrict__ W2_w,
                             const float* __restrict__ W3_w, const float* __restrict__ Win_w,
                             const float* __restrict__ Wout_w) {
    int idx = blockIdx.x * blockDim.x + threadIdx.x;
    if (idx < 49152) {
        int n = idx / 384, k = idx % 384;
        g_W1bh[idx] = __float2bfloat16_rn(W1_w[n * 512 + 128 + k]);
    } else if (idx < 65536) {
        int i = idx - 49152;
        g_W2h[i] = __float2bfloat16_rn(W2_w[i]);
    } else if (idx < 81920) {
        int i = idx - 65536;
        g_W3h[i] = __float2bfloat16_rn(W3_w[i]);
    } else if (idx < 114688) {
        int i = idx - 81920;
        int k2 = i >> 9, f = i & 511;
        g_Winp[i] = make_float2(Win_w[f * 128 + 2 * k2], Win_w[f * 128 + 2 * k2 + 1]);
    } else if (idx < 147456) {
        int i = idx - 114688;
        int k2 = i >> 7, n = i & 127;
        g_Woutp[i] = make_float2(Wout_w[n * 512 + 2 * k2], Wout_w[n * 512 + 2 * k2 + 1]);
    }
}

// hvc = h_V @ W1a^T + b1 (exact fp32); also zero g_dh
__global__ void __launch_bounds__(NT, 1)
hvc_kernel(const float* __restrict__ h_V, const float* __restrict__ W1_w,
           const float* __restrict__ W1_b) {
    extern __shared__ float smh[];
    float* sW  = smh;
    float* sHv = smh + 16384;
    const int tid = threadIdx.x;
    const int nb  = blockIdx.x * 8;
    #pragma unroll
    for (int i = 0; i < 16; ++i) {
        int id4 = i * NT + tid;
        int k4 = id4 >> 7, n = id4 & 127;
        float4 v = ((const float4*)(W1_w + (size_t)n * 512))[k4];
        sW[(4 * k4 + 0) * 128 + n] = v.x;
        sW[(4 * k4 + 1) * 128 + n] = v.y;
        sW[(4 * k4 + 2) * 128 + n] = v.z;
        sW[(4 * k4 + 3) * 128 + n] = v.w;
    }
    {
        int node = tid >> 5, q = tid & 31;
        float4 v = ((const float4*)(h_V + (size_t)(nb + node) * 128))[q];
        *(float4*)(sHv + node * 128 + 4 * q) = v;
        ((float4*)(g_dh + (size_t)nb * 128))[tid] = make_float4(0.f, 0.f, 0.f, 0.f);
    }
    __syncthreads();
    #pragma unroll
    for (int it = 0; it < 4; ++it) {
        int o = it * NT + tid;
        int node = o >> 7, col = o & 127;
        const float* hv = sHv + node * 128;
        float a = W1_b[col];
        #pragma unroll 8
        for (int k = 0; k < 128; ++k) a = fmaf(hv[k], sW[k * 128 + col], a);
        g_hvc[(size_t)(nb + node) * 128 + col] = a;
    }
}

#define CHB 18432
#define CHW (CHB / 4)

__device__ __forceinline__ void stage_B_async(unsigned dst, const __nv_bfloat16* gw,
                                              int K, int c, int tid) {
    #pragma unroll
    for (int i = 0; i < 4; ++i) {
        int idx = i * NT + tid;
        int n = idx >> 3, q = idx & 7;
        cpa16(dst + n * 144 + q * 16, gw + (size_t)n * K + c * 64 + q * 8);
    }
}

__device__ __forceinline__ void chunk_mma1(unsigned sA, unsigned sB,
                                           float* acc, unsigned aoff, unsigned boff) {
    #pragma unroll
    for (int v = 0; v < 2; ++v) {
        unsigned ah[2][2][4];
        #pragma unroll
        for (int t = 0; t < 2; ++t)
            #pragma unroll
            for (int sl = 0; sl < 2; ++sl)
                ldsm4(ah[t][sl], sA + aoff + t * 2304 + (2 * v + sl) * 32);
        #pragma unroll
        for (int u = 0; u < 8; ++u) {
            unsigned bh4[4];
            ldsm4(bh4, sB + boff + u * 1152 + v * 64);
            #pragma unroll
            for (int t = 0; t < 2; ++t) {
                float* cc = acc + (t * 8 + u) * 4;
                mma16816(cc, ah[t][0], bh4);
                mma16816(cc, ah[t][1], bh4 + 2);
            }
        }
    }
}

__device__ __forceinline__ void epi_store(char* smem, int sm_y, const float* acc,
                                          const float* badd0, const float* badd1,
                                          int m0, int nb0, int g, int t4) {
    unsigned* y = (unsigned*)(smem + sm_y);
    #pragma unroll
    for (int t = 0; t < 2; ++t) {
        int r1 = m0 + t * 16 + g, r2 = r1 + 8;
        #pragma unroll
        for (int u = 0; u < 8; ++u) {
            int n = nb0 + u * 8 + 2 * t4;
            const float* cc = acc + (t * 8 + u) * 4;
            __nv_bfloat16 ha = __float2bfloat16_rn(gelu_erf(cc[0] + badd0[n]));
            __nv_bfloat16 hb = __float2bfloat16_rn(gelu_erf(cc[1] + badd0[n + 1]));
            __nv_bfloat16 hc = __float2bfloat16_rn(gelu_erf(cc[2] + badd1[n]));
            __nv_bfloat16 hd = __float2bfloat16_rn(gelu_erf(cc[3] + badd1[n + 1]));
            int ch = n >> 6, col = (n & 63) >> 1;
            unsigned* yh = y + ch * CHW;
            yh[r1 * 36 + col] = pack2(ha, hb);
            yh[r2 * 36 + col] = pack2(hc, hd);
        }
    }
}

// ---- edge GEMM smem layout (bytes) ----
#define SM_BIAS 0
#define SM_HVC  1024
#define SM_Y1   3072
#define SM_X    (SM_Y1 + 2 * CHB)
#define SM_B    (SM_X + 2 * CHB)
#define SM_TOT  (SM_B + 2 * CHB)        // 113664 -> 2 CTAs/SM

__global__ void __launch_bounds__(NT, 2)
edge_gemm_kernel(const float* __restrict__ h_E, const float* __restrict__ mask_attend,
                 const float* __restrict__ W2_b, const float* __restrict__ W3_b,
                 int n_nodes) {
    extern __shared__ char smem[];
    const int tid = threadIdx.x;
    const int lane = tid & 31;
    const int wid = tid >> 5;
    const int g = lane >> 2, t4 = lane & 3;
    const int wm = wid >> 1, wn = wid & 1;
    const int m0 = wm * 32, nb0 = wn * 64;
    const int base = blockIdx.x * 128;
    const int n0 = base / 48;
    const unsigned sb = (unsigned)__cvta_generic_to_shared(smem);

    const unsigned aoff = (m0 + (lane & 15)) * 144 + (lane >> 4) * 16;
    const unsigned boff = (nb0 + (lane & 7)) * 144 + (lane >> 3) * 16;

    const int ar = tid >> 3, aq = tid & 7;
    const float* heb = h_E + (size_t)base * 384 + aq * 8;

    if (tid < 128) {
        ((float*)(smem + SM_BIAS))[tid]       = W2_b[tid];
        ((float*)(smem + SM_BIAS))[128 + tid] = W3_b[tid];
    }
    for (int t = tid; t < 512; t += NT) {
        int gg = t >> 7, c = t & 127;
        int nd = n0 + gg;
        ((float*)(smem + SM_HVC))[t] = (nd < n_nodes) ? g_hvc[(size_t)nd * 128 + c] : 0.f;
    }

    float acc[64];
    #pragma unroll
    for (int i = 0; i < 64; ++i) acc[i] = 0.f;

    // inline A convert: gmem fp32 -> bf16 chunk (transient registers)
    #define CONVA(c, dstb)                                                    \
      { unsigned* dh = (unsigned*)(smem + (dstb));                            \
        _Pragma("unroll")                                                     \
        for (int i = 0; i < 4; ++i) {                                         \
            const float4* p = (const float4*)(heb + (size_t)(ar + i * 32) * 384 + (c) * 64); \
            float4 v0 = p[0], v1 = p[1];                                      \
            float f[8] = {v0.x, v0.y, v0.z, v0.w, v1.x, v1.y, v1.z, v1.w};    \
            __nv_bfloat16 hb[8];                                              \
            _Pragma("unroll")                                                 \
            for (int j = 0; j < 8; ++j) hb[j] = __float2bfloat16_rn(f[j]);    \
            int o = (ar + i * 32) * 36 + aq * 4;                              \
            uint4 uh;                                                         \
            uh.x = pack2(hb[0], hb[1]); uh.y = pack2(hb[2], hb[3]);           \
            uh.z = pack2(hb[4], hb[5]); uh.w = pack2(hb[6], hb[7]);           \
            *(uint4*)(dh + o) = uh;                                           \
        } }

    // ---------- GEMM1: h_E @ W1b^T, K=384 ----------
    stage_B_async(sb + SM_B, g_W1bh, 384, 0, tid);
    CP_COMMIT();
    CONVA(0, SM_X);
    CP_WAIT0();
    __syncthreads();
    for (int c = 0; c < 6; ++c) {
        const int cur = c & 1, nxt = cur ^ 1;
        if (c < 5) {
            stage_B_async(sb + SM_B + nxt * CHB, g_W1bh, 384, c + 1, tid);
            CP_COMMIT();
            CONVA(c + 1, SM_X + nxt * CHB);
        }
        chunk_mma1(sb + SM_X + cur * CHB, sb + SM_B + cur * CHB, acc, aoff, boff);
        CP_WAIT0();
        __syncthreads();
    }

    // prefetch ALL of W2
    stage_B_async(sb + SM_B,       g_W2h, 128, 0, tid);
    stage_B_async(sb + SM_B + CHB, g_W2h, 128, 1, tid);
    CP_COMMIT();

    // epilogue 1: y1 = gelu(D + hvc[node]) -> Y1 chunks
    {
        const float* hvc = (const float*)(smem + SM_HVC);
        unsigned* y = (unsigned*)(smem + SM_Y1);
        #pragma unroll
        for (int t = 0; t < 2; ++t) {
            int rr1 = m0 + t * 16 + g, rr2 = rr1 + 8;
            const float* b0 = hvc + ((base + rr1) / 48 - n0) * 128;
            const float* b1 = hvc + ((base + rr2) / 48 - n0) * 128;
            #pragma unroll
            for (int u = 0; u < 8; ++u) {
                int n = nb0 + u * 8 + 2 * t4;
                const float* cc = acc + (t * 8 + u) * 4;
                __nv_bfloat16 ha  = __float2bfloat16_rn(gelu_erf(cc[0] + b0[n]));
                __nv_bfloat16 hb2 = __float2bfloat16_rn(gelu_erf(cc[1] + b0[n + 1]));
                __nv_bfloat16 hc  = __float2bfloat16_rn(gelu_erf(cc[2] + b1[n]));
                __nv_bfloat16 hd  = __float2bfloat16_rn(gelu_erf(cc[3] + b1[n + 1]));
                int ch = n >> 6, col = (n & 63) >> 1;
                unsigned* yh = y + ch * CHW;
                yh[rr1 * 36 + col] = pack2(ha, hb2);
                yh[rr2 * 36 + col] = pack2(hc, hd);
            }
        }
    }
    #pragma unroll
    for (int i = 0; i < 64; ++i) acc[i] = 0.f;
    CP_WAIT0();
    __syncthreads();

    // ---------- GEMM2: Y1 @ W2^T ----------
    chunk_mma1(sb + SM_Y1,       sb + SM_B,       acc, aoff, boff);
    chunk_mma1(sb + SM_Y1 + CHB, sb + SM_B + CHB, acc, aoff, boff);
    __syncthreads();

    // prefetch ALL of W3, overlapped with epilogue 2
    stage_B_async(sb + SM_B,       g_W3h, 128, 0, tid);
    stage_B_async(sb + SM_B + CHB, g_W3h, 128, 1, tid);
    CP_COMMIT();
    {
        const float* b2 = (const float*)(smem + SM_BIAS);
        epi_store(smem, SM_X, acc, b2, b2, m0, nb0, g, t4);
    }
    #pragma unroll
    for (int i = 0; i < 64; ++i) acc[i] = 0.f;
    CP_WAIT0();
    __syncthreads();

    // ---------- GEMM3: Y2 @ W3^T ----------
    chunk_mma1(sb + SM_X,       sb + SM_B,       acc, aoff, boff);
    chunk_mma1(sb + SM_X + CHB, sb + SM_B + CHB, acc, aoff, boff);
    __syncthreads();

    // epilogue 3: msg*(mask) -> sMsg [n][129]; segment sums -> g_dh
    {
        const float* b3 = (const float*)(smem + SM_BIAS) + 128;
        float* sMsg = (float*)(smem + SM_Y1);
        #pragma unroll
        for (int t = 0; t < 2; ++t) {
            int r1 = m0 + t * 16 + g, r2 = r1 + 8;
            float mk1 = mask_attend[base + r1];
            float mk2 = mask_attend[base + r2];
            #pragma unroll
            for (int u = 0; u < 8; ++u) {
                int n = nb0 + u * 8 + 2 * t4;
                const float* cc = acc + (t * 8 + u) * 4;
                sMsg[n * 129 + r1]       = (cc[0] + b3[n])     * mk1;
                sMsg[(n + 1) * 129 + r1] = (cc[1] + b3[n + 1]) * mk1;
                sMsg[n * 129 + r2]       = (cc[2] + b3[n])     * mk2;
                sMsg[(n + 1) * 129 + r2] = (cc[3] + b3[n + 1]) * mk2;
            }
        }
    }
    __syncthreads();
    if (tid < 128) {
        const float* sMsg = (const float*)(smem + SM_Y1);
        int col = tid;
        #pragma unroll
        for (int gg = 0; gg < 4; ++gg) {
            int ng = n0 + gg;
            if (ng >= n_nodes) break;
            int lo = ng * 48 - base, hi = lo + 48;
            if (lo < 0) lo = 0;
            if (hi > 128) hi = 128;
            if (lo < hi) {
                float s = 0.f;
                for (int r = lo; r < hi; ++r) s += sMsg[col * 129 + r];
                atomicAdd(&g_dh[(size_t)ng * 128 + col], s);
            }
        }
    }
}

// ---- FFN (fp32 f32x2) with fused LN1 ----
#define K2_H   0
#define K2_F   4096
#define K2_O   20480
#define SM2_BYTES  (24576 * 4)
#define INNERG(J, XB, XSTRIDE, WP, WROWF)                              \
  {                                                                    \
    ulonglong2 va = __ldg((const ulonglong2*)(WP));                    \
    ulonglong2 vb = __ldg((const ulonglong2*)((WP) + (WROWF)));        \
    _Pragma("unroll")                                                  \
    for (int j = 0; j < (J); ++j) {                                    \
      u64 xa, xb; lds2(xa, xb, (XB) + j * (XSTRIDE));                  \
      fma2(acc[j][0], xa, va.x); fma2(acc[j][1], xa, va.y);            \
      fma2(acc[j][0], xb, vb.x); fma2(acc[j][1], xb, vb.y);            \
    }                                                                  \
  }

__global__ void __launch_bounds__(NT, 1)
ffn_kernel(const float* __restrict__ h_V, const float* __restrict__ mask_V,
           const float* __restrict__ ln1_g, const float* __restrict__ ln1_b,
           const float* __restrict__ Win_b, const float* __restrict__ Wout_b,
           const float* __restrict__ ln2_g, const float* __restrict__ ln2_b,
           float* __restrict__ out)
{
    extern __shared__ float smf[];
    const int tid = threadIdx.x;
    const int tx  = tid & 31;
    const int ty  = tid >> 5;
    const int wm  = ty >> 1;
    const int wn  = ty & 1;
    const int m0  = wm * 8;
    const int n0  = wn * 64 + 2 * tx;
    const int nb  = blockIdx.x * 32;

    const unsigned sbase = (unsigned)__cvta_generic_to_shared(smf);
    float* sH = smf + K2_H;
    float* sF = smf + K2_F;
    float* sO = smf + K2_O;
    const float* gWin  = (const float*)g_Winp;
    const float* gWout = (const float*)g_Woutp + 2 * n0;

    // fused LN1: each warp computes 4 rows of H = LN(h_V + dh/30)
    #pragma unroll
    for (int j = 0; j < 4; ++j) {
        int r = ty * 4 + j;
        float4 dv = ((const float4*)(g_dh + (size_t)(nb + r) * 128))[tx];
        float4 hv = ((const float4*)(h_V + (size_t)(nb + r) * 128))[tx];
        float v0 = hv.x + dv.x * (1.0f / 30.0f);
        float v1 = hv.y + dv.y * (1.0f / 30.0f);
        float v2 = hv.z + dv.z * (1.0f / 30.0f);
        float v3 = hv.w + dv.w * (1.0f / 30.0f);
        float s = v0 + v1 + v2 + v3;
        float s2 = v0 * v0 + v1 * v1 + v2 * v2 + v3 * v3;
        #pragma unroll
        for (int off = 16; off > 0; off >>= 1) {
            s  += __shfl_xor_sync(0xffffffffu, s,  off);
            s2 += __shfl_xor_sync(0xffffffffu, s2, off);
        }
        float mean = s * (1.0f / 128.0f);
        float rstd = rsqrtf(s2 * (1.0f / 128.0f) - mean * mean + 1e-5f);
        float4 gg = ((const float4*)ln1_g)[tx];
        float4 bb = ((const float4*)ln1_b)[tx];
        float4 o;
        o.x = (v0 - mean) * rstd * gg.x + bb.x;
        o.y = (v1 - mean) * rstd * gg.y + bb.y;
        o.z = (v2 - mean) * rstd * gg.z + bb.z;
        o.w = (v3 - mean) * rstd * gg.w + bb.w;
        *(float4*)(sH + r * 128 + 4 * tx) = o;
    }
    __syncthreads();

    u64 acc[8][2];
    for (int nblk = 0; nblk < 4; ++nblk) {
        #pragma unroll
        for (int j = 0; j < 8; ++j) { acc[j][0] = 0ULL; acc[j][1] = 0ULL; }
        {
            const unsigned xrow = sbase + K2_H * 4 + m0 * 512;
            const float* wp = gWin + nblk * 256 + 2 * n0;
            #pragma unroll 4
            for (int it = 0; it < 32; ++it)
                INNERG(8, xrow + it * 16, 512, wp + it * 2048, 1024);
        }
        float2 bv = *(const float2*)(Win_b + nblk * 128 + n0);
        #pragma unroll
        for (int j = 0; j < 8; ++j) {
            float2 r;
            r.x = gelu_erf(hadd(acc[j][0]) + bv.x);
            r.y = gelu_erf(hadd(acc[j][1]) + bv.y);
            *(float2*)(sF + (m0 + j) * 512 + nblk * 128 + n0) = r;
        }
    }
    __syncthreads();

    #pragma unroll
    for (int j = 0; j < 8; ++j) { acc[j][0] = 0ULL; acc[j][1] = 0ULL; }
    for (int kt = 0; kt < 4; ++kt) {
        const unsigned xrow = sbase + K2_F * 4 + m0 * 2048;
        const float* wp = gWout + kt * 16384;
        #pragma unroll 4
        for (int it = 0; it < 32; ++it)
            INNERG(8, xrow + kt * 512 + it * 16, 2048, wp + it * 512, 256);
    }
    {
        float2 bv = *(const float2*)(Wout_b + n0);
        #pragma unroll
        for (int j = 0; j < 8; ++j) {
            float2 r;
            r.x = hadd(acc[j][0]) + bv.x;
            r.y = hadd(acc[j][1]) + bv.y;
            *(float2*)(sO + (m0 + j) * 128 + n0) = r;
        }
    }
    __syncthreads();

    #pragma unroll
    for (int rr = 0; rr < 4; ++rr) {
        int r = ty + rr * 8;
        float v[4];
        float s = 0.f, s2 = 0.f;
        #pragma unroll
        for (int i = 0; i < 4; ++i) {
            int n = tx + i * 32;
            v[i] = sH[r * 128 + n] + sO[r * 128 + n];
            s += v[i]; s2 += v[i] * v[i];
        }
        #pragma unroll
        for (int off = 16; off > 0; off >>= 1) {
            s  += __shfl_xor_sync(0xffffffffu, s,  off);
            s2 += __shfl_xor_sync(0xffffffffu, s2, off);
        }
        float mean = s * (1.0f / 128.0f);
        float rstd = rsqrtf(s2 * (1.0f / 128.0f) - mean * mean + 1e-5f);
        float mv = mask_V[nb + r];
        #pragma unroll
        for (int i = 0; i < 4; ++i) {
            int n = tx + i * 32;
            out[(size_t)(nb + r) * Hdim + n] =
                mv * ((v[i] - mean) * rstd * ln2_g[n] + ln2_b[n]);
        }
    }
}

extern "C" void kernel_launch(void* const* d_in, const int* in_sizes, int n_in,
                              void* d_out, int out_size) {
    const float* h_V         = (const float*)d_in[0];
    const float* h_E         = (const float*)d_in[1];
    const float* mask_V      = (const float*)d_in[2];
    const float* mask_attend = (const float*)d_in[3];
    const float* W1_w        = (const float*)d_in[4];
    const float* W1_b        = (const float*)d_in[5];
    const float* W2_w        = (const float*)d_in[6];
    const float* W2_b        = (const float*)d_in[7];
    const float* W3_w        = (const float*)d_in[8];
    const float* W3_b        = (const float*)d_in[9];
    const float* ln1_g       = (const float*)d_in[10];
    const float* ln1_b       = (const float*)d_in[11];
    const float* ln2_g       = (const float*)d_in[12];
    const float* ln2_b       = (const float*)d_in[13];
    const float* Win_w       = (const float*)d_in[14];
    const float* Win_b       = (const float*)d_in[15];
    const float* Wout_w      = (const float*)d_in[16];
    const float* Wout_b      = (const float*)d_in[17];

    int nodes = in_sizes[0] / Hdim;        // 4096
    int tiles = (nodes * KNB + 127) / 128; // 1536

    prep_weights<<<576, 256>>>(W1_w, W2_w, W3_w, Win_w, Wout_w);

    cudaFuncSetAttribute(hvc_kernel, cudaFuncAttributeMaxDynamicSharedMemorySize, 73728);
    hvc_kernel<<<nodes / 8, NT, 73728>>>(h_V, W1_w, W1_b);

    cudaFuncSetAttribute(edge_gemm_kernel, cudaFuncAttributeMaxDynamicSharedMemorySize, SM_TOT);
    edge_gemm_kernel<<<tiles, NT, SM_TOT>>>(h_E, mask_attend, W2_b, W3_b, nodes);

    cudaFuncSetAttribute(ffn_kernel, cudaFuncAttributeMaxDynamicSharedMemorySize, SM2_BYTES);
    ffn_kernel<<<nodes / 32, NT, SM2_BYTES>>>(h_V, mask_V, ln1_g, ln1_b,
                                              Win_b, Wout_b, ln2_g, ln2_b, (float*)d_out);
}